// round 2
// baseline (speedup 1.0000x reference)
#include <cuda_runtime.h>
#include <math.h>

// ---------------- problem constants ----------------
#define BSZ   8
#define DIM   384
#define HH    56
#define WW    56
#define HWQ   3136          // 56*56
#define NH    6
#define DH    64
#define GRP   3             // D_GROUPS
#define NGD   128           // DIM / GRP
#define HO    28
#define WO    28
#define LO    784           // 28*28
#define SCALE 0.125f

// ---------------- scratch (device globals, no allocs) ----------------
__device__ float  d_q   [(size_t)BSZ * DIM * HWQ];     // (B,384,3136)
__device__ float  d_off [(size_t)BSZ * GRP * NGD * LO];// (24,128,784)
__device__ float4 d_grid[(size_t)BSZ * GRP * LO];      // gx,gy,mod per (n,pix)
__device__ float  d_xs  [(size_t)BSZ * DIM * LO];      // (B,384,784)
__device__ float  d_kv  [(size_t)BSZ * 2 * DIM * LO];  // (B,768,784)
__device__ float  d_attn[(size_t)BSZ * DIM * HWQ];     // (B,384,3136)

// ---------------- generic batched GEMM: Y[b] = W (MxK) @ X[b] (KxN) (+bias) ----------------
#define GBM 64
#define GBN 64
#define GBK 16
__global__ void gemm_kernel(const float* __restrict__ W, const float* __restrict__ X,
                            float* __restrict__ Y, const float* __restrict__ bias,
                            int M, int N, int K) {
    __shared__ __align__(16) float As[GBK][GBM];
    __shared__ __align__(16) float Bs[GBK][GBN];
    const int bz = blockIdx.z;
    const float* Xb = X + (size_t)bz * K * N;
    float*       Yb = Y + (size_t)bz * M * N;
    const int m0 = blockIdx.y * GBM, n0 = blockIdx.x * GBN;
    const int tid = threadIdx.x;
    const int tx = tid & 15, ty = tid >> 4;
    float acc[4][4] = {};

    for (int k0 = 0; k0 < K; k0 += GBK) {
        // load A tile (W), transpose into As[k][m]
        {
            int m = tid >> 2, kk = (tid & 3) * 4;
            float4 w4 = *(const float4*)&W[(size_t)(m0 + m) * K + k0 + kk];
            As[kk + 0][m] = w4.x; As[kk + 1][m] = w4.y;
            As[kk + 2][m] = w4.z; As[kk + 3][m] = w4.w;
        }
        // load B tile
        {
            int r = tid >> 4, cc = (tid & 15) * 4;
            int n = n0 + cc;
            float4 b4 = make_float4(0.f, 0.f, 0.f, 0.f);
            const float* row = &Xb[(size_t)(k0 + r) * N];
            if (n + 3 < N) {
                b4 = *(const float4*)&row[n];
            } else {
                if (n + 0 < N) b4.x = row[n + 0];
                if (n + 1 < N) b4.y = row[n + 1];
                if (n + 2 < N) b4.z = row[n + 2];
                if (n + 3 < N) b4.w = row[n + 3];
            }
            Bs[r][cc + 0] = b4.x; Bs[r][cc + 1] = b4.y;
            Bs[r][cc + 2] = b4.z; Bs[r][cc + 3] = b4.w;
        }
        __syncthreads();
        #pragma unroll
        for (int k = 0; k < GBK; k++) {
            float4 a4 = *(const float4*)&As[k][ty * 4];
            float4 b4 = *(const float4*)&Bs[k][tx * 4];
            acc[0][0] = fmaf(a4.x, b4.x, acc[0][0]); acc[0][1] = fmaf(a4.x, b4.y, acc[0][1]);
            acc[0][2] = fmaf(a4.x, b4.z, acc[0][2]); acc[0][3] = fmaf(a4.x, b4.w, acc[0][3]);
            acc[1][0] = fmaf(a4.y, b4.x, acc[1][0]); acc[1][1] = fmaf(a4.y, b4.y, acc[1][1]);
            acc[1][2] = fmaf(a4.y, b4.z, acc[1][2]); acc[1][3] = fmaf(a4.y, b4.w, acc[1][3]);
            acc[2][0] = fmaf(a4.z, b4.x, acc[2][0]); acc[2][1] = fmaf(a4.z, b4.y, acc[2][1]);
            acc[2][2] = fmaf(a4.z, b4.z, acc[2][2]); acc[2][3] = fmaf(a4.z, b4.w, acc[2][3]);
            acc[3][0] = fmaf(a4.w, b4.x, acc[3][0]); acc[3][1] = fmaf(a4.w, b4.y, acc[3][1]);
            acc[3][2] = fmaf(a4.w, b4.z, acc[3][2]); acc[3][3] = fmaf(a4.w, b4.w, acc[3][3]);
        }
        __syncthreads();
    }
    #pragma unroll
    for (int i = 0; i < 4; i++) {
        int m = m0 + ty * 4 + i;
        float bv = bias ? bias[m] : 0.f;
        #pragma unroll
        for (int j = 0; j < 4; j++) {
            int n = n0 + tx * 4 + j;
            if (n < N) Yb[(size_t)m * N + n] = acc[i][j] + bv;
        }
    }
}

// ---------------- depthwise 5x5 s2 + bias + BN + exact GELU ----------------
__global__ void dw_bn_gelu_kernel(const float* __restrict__ q,
                                  const float* __restrict__ dw_w, const float* __restrict__ dw_b,
                                  const float* __restrict__ bn_w, const float* __restrict__ bn_b,
                                  const float* __restrict__ bn_mean, const float* __restrict__ bn_var,
                                  float* __restrict__ off) {
    int idx = blockIdx.x * blockDim.x + threadIdx.x;
    const int TOT = BSZ * GRP * NGD * LO;
    if (idx >= TOT) return;
    int pix = idx % LO;
    int c   = (idx / LO) % NGD;
    int n   = idx / (LO * NGD);
    int oy = pix / WO, ox = pix % WO;
    int b = n / GRP, g = n % GRP;
    const float* plane = q + ((size_t)(b * DIM + g * NGD + c)) * HWQ;
    const float* wk = dw_w + c * 25;
    float s = 0.f;
    #pragma unroll
    for (int ky = 0; ky < 5; ky++) {
        int iy = oy * 2 + ky - 2;
        if (iy < 0 || iy >= HH) continue;
        #pragma unroll
        for (int kx = 0; kx < 5; kx++) {
            int ix = ox * 2 + kx - 2;
            if (ix >= 0 && ix < WW) s = fmaf(plane[iy * WW + ix], wk[ky * 5 + kx], s);
        }
    }
    s += dw_b[c];
    s = (s - bn_mean[c]) * (bn_w[c] * rsqrtf(bn_var[c] + 1e-6f)) + bn_b[c];
    s = 0.5f * s * (1.0f + erff(s * 0.70710678118654752f));   // exact gelu
    off[idx] = s;
}

// ---------------- pointwise 128->3 + offset/grid math ----------------
__global__ void pw_grid_kernel(const float* __restrict__ off, const float* __restrict__ pw_w,
                               float4* __restrict__ grid4) {
    int idx = blockIdx.x * blockDim.x + threadIdx.x;
    const int TOT = BSZ * GRP * LO;
    if (idx >= TOT) return;
    int n = idx / LO, pix = idx % LO;
    const float* base = off + (size_t)n * NGD * LO + pix;
    float o0 = 0.f, o1 = 0.f, o2 = 0.f;
    #pragma unroll 4
    for (int c = 0; c < NGD; c++) {
        float v = base[(size_t)c * LO];
        o0 = fmaf(v, pw_w[c], o0);
        o1 = fmaf(v, pw_w[NGD + c], o1);
        o2 = fmaf(v, pw_w[2 * NGD + c], o2);
    }
    int oy = pix / WO, ox = pix % WO;
    float ry = ((0.5f + (float)oy) / (float)HO) * 2.f - 1.f;
    float rx = ((0.5f + (float)ox) / (float)WO) * 2.f - 1.f;
    float posy = tanhf(o0) * (2.0f / (float)HO) + ry;   // OFFSET_RANGE_FACTOR * rng
    float posx = tanhf(o1) * (2.0f / (float)WO) + rx;
    float gx = (posx + 1.f) * 0.5f * (float)(WW - 1);
    float gy = (posy + 1.f) * 0.5f * (float)(HH - 1);
    float sig = 1.f / (1.f + expf(-o2));
    float mod = 1.f / (1.f + expf(-sig));               // reference applies sigmoid twice
    grid4[idx] = make_float4(gx, gy, mod, 0.f);
}

// ---------------- bilinear grid sample (zero-pad border) * modulation ----------------
__global__ void sample_kernel(const float* __restrict__ x, const float4* __restrict__ grid4,
                              float* __restrict__ xs) {
    int nc = blockIdx.x;                       // 0 .. 24*128-1
    int pix = blockIdx.y * blockDim.x + threadIdx.x;
    if (pix >= LO) return;
    int c = nc & (NGD - 1), n = nc >> 7;
    int b = n / GRP, g = n % GRP;
    float4 gq = grid4[(size_t)n * LO + pix];
    float gx = gq.x, gy = gq.y, mod = gq.z;
    float x0f = floorf(gx), y0f = floorf(gy);
    float x1f = x0f + 1.f, y1f = y0f + 1.f;
    const float* plane = x + ((size_t)(b * DIM + g * NGD + c)) * HWQ;

    float t00 = 0.f, t01 = 0.f, t10 = 0.f, t11 = 0.f;
    bool vx0 = (x0f >= 0.f) && (x0f <= (float)(WW - 1));
    bool vx1 = (x1f >= 0.f) && (x1f <= (float)(WW - 1));
    bool vy0 = (y0f >= 0.f) && (y0f <= (float)(HH - 1));
    bool vy1 = (y1f >= 0.f) && (y1f <= (float)(HH - 1));
    int xi0 = (int)fminf(fmaxf(x0f, 0.f), (float)(WW - 1));
    int xi1 = (int)fminf(fmaxf(x1f, 0.f), (float)(WW - 1));
    int yi0 = (int)fminf(fmaxf(y0f, 0.f), (float)(HH - 1));
    int yi1 = (int)fminf(fmaxf(y1f, 0.f), (float)(HH - 1));
    if (vy0 && vx0) t00 = plane[yi0 * WW + xi0];
    if (vy1 && vx0) t10 = plane[yi1 * WW + xi0];
    if (vy0 && vx1) t01 = plane[yi0 * WW + xi1];
    if (vy1 && vx1) t11 = plane[yi1 * WW + xi1];

    float v = t00 * (x1f - gx) * (y1f - gy)
            + t10 * (x1f - gx) * (gy - y0f)
            + t01 * (gx - x0f) * (y1f - gy)
            + t11 * (gx - x0f) * (gy - y0f);
    xs[((size_t)(b * DIM + g * NGD + c)) * LO + pix] = v * mod;
}

// ---------------- flash-style attention: per-thread query, online softmax ----------------
#define QT 128
#define KT 56
__global__ void attn_kernel(const float* __restrict__ q, const float* __restrict__ kv,
                            float* __restrict__ out) {
    extern __shared__ __align__(16) float sm[];
    float* qT = sm;                 // [64][128]  (d-major, conflict-free per-thread column)
    float* kt = sm + 64 * QT;       // [64][56]   (d-major, broadcast reads)
    float* vt = kt + 64 * KT;       // [64][56]
    const int qb = blockIdx.x * QT;
    const int h = blockIdx.y, b = blockIdx.z;
    const int tid = threadIdx.x;    // 128 threads

    // load Q tile (pre-scaled)
    const float* qbase = q + ((size_t)(b * DIM + h * DH)) * HWQ + qb;
    for (int i = tid; i < DH * QT; i += QT) {
        int d = i >> 7, col = i & (QT - 1);
        qT[i] = (qb + col < HWQ) ? qbase[(size_t)d * HWQ + col] * SCALE : 0.f;
    }

    float m = -1e30f, l = 0.f;
    float acc[DH];
    #pragma unroll
    for (int d = 0; d < DH; d++) acc[d] = 0.f;

    const float* kbaseP = kv + ((size_t)(b * 2 * DIM + h * DH)) * LO;
    const float* vbaseP = kv + ((size_t)(b * 2 * DIM + DIM + h * DH)) * LO;

    for (int t = 0; t < LO / KT; t++) {       // 14 tiles of 56 keys
        int kb = t * KT;
        __syncthreads();
        for (int i = tid; i < DH * KT; i += QT) {
            int d = i / KT, j = i % KT;
            kt[i] = kbaseP[(size_t)d * LO + kb + j];
            vt[i] = vbaseP[(size_t)d * LO + kb + j];
        }
        __syncthreads();

        float s[KT];
        #pragma unroll
        for (int j = 0; j < KT; j++) s[j] = 0.f;
        for (int d0 = 0; d0 < DH; d0 += 8) {
            float qr[8];
            #pragma unroll
            for (int dd = 0; dd < 8; dd++) qr[dd] = qT[(d0 + dd) * QT + tid];
            #pragma unroll
            for (int dd = 0; dd < 8; dd++) {
                const float4* krow = (const float4*)(kt + (d0 + dd) * KT);
                #pragma unroll
                for (int j4 = 0; j4 < KT / 4; j4++) {
                    float4 k4 = krow[j4];
                    s[j4 * 4 + 0] = fmaf(qr[dd], k4.x, s[j4 * 4 + 0]);
                    s[j4 * 4 + 1] = fmaf(qr[dd], k4.y, s[j4 * 4 + 1]);
                    s[j4 * 4 + 2] = fmaf(qr[dd], k4.z, s[j4 * 4 + 2]);
                    s[j4 * 4 + 3] = fmaf(qr[dd], k4.w, s[j4 * 4 + 3]);
                }
            }
        }
        float mt = m;
        #pragma unroll
        for (int j = 0; j < KT; j++) mt = fmaxf(mt, s[j]);
        float corr = __expf(m - mt);
        m = mt;
        float ps = 0.f;
        #pragma unroll
        for (int j = 0; j < KT; j++) { s[j] = __expf(s[j] - mt); ps += s[j]; }
        l = l * corr + ps;
        #pragma unroll
        for (int d = 0; d < DH; d++) {
            float a = acc[d] * corr;
            const float4* vrow = (const float4*)(vt + d * KT);
            #pragma unroll
            for (int j4 = 0; j4 < KT / 4; j4++) {
                float4 v4 = vrow[j4];
                a = fmaf(s[j4 * 4 + 0], v4.x, a);
                a = fmaf(s[j4 * 4 + 1], v4.y, a);
                a = fmaf(s[j4 * 4 + 2], v4.z, a);
                a = fmaf(s[j4 * 4 + 3], v4.w, a);
            }
            acc[d] = a;
        }
    }
    int qq = qb + tid;
    if (qq < HWQ) {
        float inv = 1.f / l;
        float* ob = out + ((size_t)(b * DIM + h * DH)) * HWQ + qq;
        #pragma unroll
        for (int d = 0; d < DH; d++) ob[(size_t)d * HWQ] = acc[d] * inv;
    }
}

// ---------------- launch ----------------
extern "C" void kernel_launch(void* const* d_in, const int* in_sizes, int n_in,
                              void* d_out, int out_size) {
    const float* x      = (const float*)d_in[0];
    const float* q_w    = (const float*)d_in[1];
    const float* kv_w   = (const float*)d_in[2];
    const float* proj_w = (const float*)d_in[3];
    const float* proj_b = (const float*)d_in[4];
    const float* dw_w   = (const float*)d_in[5];
    const float* dw_b   = (const float*)d_in[6];
    const float* bn_w   = (const float*)d_in[7];
    const float* bn_b   = (const float*)d_in[8];
    const float* bn_mean= (const float*)d_in[9];
    const float* bn_var = (const float*)d_in[10];
    const float* pw_w   = (const float*)d_in[11];
    float* out = (float*)d_out;

    float *q, *off, *xs, *kvb, *attn; float4* grid;
    cudaGetSymbolAddress((void**)&q,    d_q);
    cudaGetSymbolAddress((void**)&off,  d_off);
    cudaGetSymbolAddress((void**)&grid, d_grid);
    cudaGetSymbolAddress((void**)&xs,   d_xs);
    cudaGetSymbolAddress((void**)&kvb,  d_kv);
    cudaGetSymbolAddress((void**)&attn, d_attn);

    // K1: q = q_w @ x   (per batch)
    dim3 g1(HWQ / GBN, DIM / GBM, BSZ);
    gemm_kernel<<<g1, 256>>>(q_w, x, q, nullptr, DIM, HWQ, DIM);

    // K2: depthwise conv + bias + BN + gelu
    {
        int tot = BSZ * GRP * NGD * LO;
        dw_bn_gelu_kernel<<<(tot + 255) / 256, 256>>>(q, dw_w, dw_b, bn_w, bn_b,
                                                      bn_mean, bn_var, off);
    }
    // K3a: pointwise + grid computation
    {
        int tot = BSZ * GRP * LO;
        pw_grid_kernel<<<(tot + 255) / 256, 256>>>(off, pw_w, grid);
    }
    // K3b: bilinear sampling * modulation
    {
        dim3 g((BSZ * GRP * NGD), (LO + 255) / 256);
        sample_kernel<<<g, 256>>>(x, grid, xs);
    }
    // K4: kv = kv_w @ xs
    {
        dim3 g((LO + GBN - 1) / GBN, (2 * DIM) / GBM, BSZ);
        gemm_kernel<<<g, 256>>>(kv_w, xs, kvb, nullptr, 2 * DIM, LO, DIM);
    }
    // K5: attention
    {
        dim3 g((HWQ + QT - 1) / QT, NH, BSZ);
        size_t smem = (size_t)(64 * QT + 2 * 64 * KT) * sizeof(float);  // 61440 B
        cudaFuncSetAttribute(attn_kernel, cudaFuncAttributeMaxDynamicSharedMemorySize, (int)smem);
        attn_kernel<<<g, QT, smem>>>(q, kvb, attn);
    }
    // K6: out = proj_w @ attn + proj_b
    gemm_kernel<<<g1, 256>>>(proj_w, attn, out, proj_b, DIM, HWQ, DIM);
}

// round 5
// speedup vs baseline: 1.7328x; 1.7328x over previous
#include <cuda_runtime.h>
#include <cuda_bf16.h>
#include <math.h>
#include <stdint.h>

// ---------------- problem constants ----------------
#define BSZ   8
#define DIM   384
#define HH    56
#define WW    56
#define HWQ   3136          // 56*56
#define NH    6
#define DH    64
#define GRP   3             // D_GROUPS
#define NGD   128           // DIM / GRP
#define HO    28
#define WO    28
#define LO    784           // 28*28
#define SCALE 0.125f

// ---------------- scratch (device globals, no allocs) ----------------
__device__ float  d_q   [(size_t)BSZ * DIM * HWQ];     // (B,384,3136) ch-major
__device__ float  d_off [(size_t)BSZ * GRP * NGD * LO];
__device__ float4 d_grid[(size_t)BSZ * GRP * LO];
__device__ float  d_xs  [(size_t)BSZ * DIM * LO];      // (B,384,784) ch-major
__device__ float  d_kv  [(size_t)BSZ * 2 * DIM * LO];  // (B,768,784) ch-major
__device__ float  d_attn[(size_t)BSZ * HWQ * DIM];     // (B,3136,384) pix-major!

// ---------------- bf16 split helpers ----------------
__device__ __forceinline__ void split1(float x, unsigned short& h, unsigned short& l) {
    __nv_bfloat16 bh = __float2bfloat16(x);
    float r = x - __bfloat162float(bh);
    __nv_bfloat16 bl = __float2bfloat16(r);
    h = __bfloat16_as_ushort(bh);
    l = __bfloat16_as_ushort(bl);
}
__device__ __forceinline__ void split_pack(float x, float y, uint32_t& ph, uint32_t& pl) {
    unsigned short xh, xl, yh, yl;
    split1(x, xh, xl); split1(y, yh, yl);
    ph = ((uint32_t)yh << 16) | xh;
    pl = ((uint32_t)yl << 16) | xl;
}
__device__ __forceinline__ void mma_bf16(float* c, const uint32_t* a, const uint32_t* b) {
    asm volatile(
        "mma.sync.aligned.m16n8k16.row.col.f32.bf16.bf16.f32 "
        "{%0,%1,%2,%3}, {%4,%5,%6,%7}, {%8,%9}, {%0,%1,%2,%3};\n"
        : "+f"(c[0]), "+f"(c[1]), "+f"(c[2]), "+f"(c[3])
        : "r"(a[0]), "r"(a[1]), "r"(a[2]), "r"(a[3]), "r"(b[0]), "r"(b[1]));
}

// ==================================================================
// GEMM: Y[b] = W(MxK=384) @ X[b](384xN)  (+bias), 3xBF16 split mma.
// BT=false: X is [K][N] (N contiguous). BT=true: X is [N][K] (K contiguous).
// ==================================================================
#define SST 24   // smem row stride in halves (conflict-free: bank=12g+t)
template<bool BT>
__global__ __launch_bounds__(256, 2) void gemm_mma(const float* __restrict__ W,
                                                   const float* __restrict__ X,
                                                   float* __restrict__ Y,
                                                   const float* __restrict__ bias,
                                                   int M, int N) {
    const int KD = 384;
    __shared__ unsigned short Ah[128 * SST], Al[128 * SST];
    __shared__ unsigned short Bh[128 * SST], Bl[128 * SST];
    const int bz = blockIdx.z;
    const float* Xb = X + (size_t)bz * KD * N;
    float*       Yb = Y + (size_t)bz * M * N;
    const int m0 = blockIdx.y * 128, n0 = blockIdx.x * 128;
    const int tid = threadIdx.x, lane = tid & 31, wid = tid >> 5;
    const int wm = wid & 3, wn = wid >> 2;          // 4 warps M x 2 warps N
    const int g = lane >> 2, tq = lane & 3;

    float c[2][8][4];
    #pragma unroll
    for (int i = 0; i < 2; i++)
        #pragma unroll
        for (int j = 0; j < 8; j++)
            #pragma unroll
            for (int k = 0; k < 4; k++) c[i][j][k] = 0.f;

    // staging assignments
    const int arow = tid >> 1, acol = (tid & 1) * 8;     // A: 128 rows x 16k
    const int bro  = tid >> 4, bnb  = (tid & 15) * 8;    // B (NN): 16k x 128n
    const int bn2  = tid >> 1, bk2  = (tid & 1) * 8;     // B (NT): 128n x 16k

    float4 ar0, ar1, br0, br1;
    const float4 z4 = make_float4(0.f, 0.f, 0.f, 0.f);

    auto LOADA = [&](int kc) {
        const float* p = &W[(size_t)(m0 + arow) * KD + kc * 16 + acol];
        ar0 = *(const float4*)p; ar1 = *(const float4*)(p + 4);
    };
    auto LOADB = [&](int kc) {
        if (!BT) {
            const float* p = &Xb[(size_t)(kc * 16 + bro) * N + n0 + bnb];
            br0 = (n0 + bnb     < N) ? *(const float4*)p       : z4;
            br1 = (n0 + bnb + 4 < N) ? *(const float4*)(p + 4) : z4;
        } else {
            bool v = (n0 + bn2 < N);
            const float* p = &Xb[(size_t)(n0 + bn2) * KD + kc * 16 + bk2];
            br0 = v ? *(const float4*)p : z4;
            br1 = v ? *(const float4*)(p + 4) : z4;
        }
    };
    auto STORE = [&]() {
        float av[8] = {ar0.x, ar0.y, ar0.z, ar0.w, ar1.x, ar1.y, ar1.z, ar1.w};
        #pragma unroll
        for (int j = 0; j < 8; j++) {
            unsigned short h, l; split1(av[j], h, l);
            Ah[arow * SST + acol + j] = h; Al[arow * SST + acol + j] = l;
        }
        float bv[8] = {br0.x, br0.y, br0.z, br0.w, br1.x, br1.y, br1.z, br1.w};
        #pragma unroll
        for (int j = 0; j < 8; j++) {
            unsigned short h, l; split1(bv[j], h, l);
            if (!BT) { Bh[(bnb + j) * SST + bro] = h; Bl[(bnb + j) * SST + bro] = l; }
            else     { Bh[bn2 * SST + bk2 + j]  = h; Bl[bn2 * SST + bk2 + j]  = l; }
        }
    };

    LOADA(0); LOADB(0); STORE();
    for (int kc = 0; kc < 24; kc++) {
        __syncthreads();
        if (kc < 23) { LOADA(kc + 1); LOADB(kc + 1); }
        uint32_t ah[2][4], al[2][4];
        #pragma unroll
        for (int mt = 0; mt < 2; mt++) {
            int rb = wm * 32 + mt * 16;
            ah[mt][0] = *(const uint32_t*)&Ah[(rb + g) * SST + 2 * tq];
            ah[mt][1] = *(const uint32_t*)&Ah[(rb + 8 + g) * SST + 2 * tq];
            ah[mt][2] = *(const uint32_t*)&Ah[(rb + g) * SST + 2 * tq + 8];
            ah[mt][3] = *(const uint32_t*)&Ah[(rb + 8 + g) * SST + 2 * tq + 8];
            al[mt][0] = *(const uint32_t*)&Al[(rb + g) * SST + 2 * tq];
            al[mt][1] = *(const uint32_t*)&Al[(rb + 8 + g) * SST + 2 * tq];
            al[mt][2] = *(const uint32_t*)&Al[(rb + g) * SST + 2 * tq + 8];
            al[mt][3] = *(const uint32_t*)&Al[(rb + 8 + g) * SST + 2 * tq + 8];
        }
        #pragma unroll
        for (int nt = 0; nt < 8; nt++) {
            int nb = wn * 64 + nt * 8;
            uint32_t bh[2], bl[2];
            bh[0] = *(const uint32_t*)&Bh[(nb + g) * SST + 2 * tq];
            bh[1] = *(const uint32_t*)&Bh[(nb + g) * SST + 2 * tq + 8];
            bl[0] = *(const uint32_t*)&Bl[(nb + g) * SST + 2 * tq];
            bl[1] = *(const uint32_t*)&Bl[(nb + g) * SST + 2 * tq + 8];
            #pragma unroll
            for (int mt = 0; mt < 2; mt++) {
                mma_bf16(c[mt][nt], ah[mt], bh);
                mma_bf16(c[mt][nt], al[mt], bh);
                mma_bf16(c[mt][nt], ah[mt], bl);
            }
        }
        __syncthreads();
        if (kc < 23) STORE();
    }

    #pragma unroll
    for (int mt = 0; mt < 2; mt++) {
        int row0 = m0 + wm * 32 + mt * 16 + g;
        int row1 = row0 + 8;
        float bv0 = bias ? bias[row0] : 0.f;
        float bv1 = bias ? bias[row1] : 0.f;
        #pragma unroll
        for (int nt = 0; nt < 8; nt++) {
            int col = n0 + wn * 64 + nt * 8 + 2 * tq;
            if (col < N) {
                Yb[(size_t)row0 * N + col]     = c[mt][nt][0] + bv0;
                Yb[(size_t)row0 * N + col + 1] = c[mt][nt][1] + bv0;
                Yb[(size_t)row1 * N + col]     = c[mt][nt][2] + bv1;
                Yb[(size_t)row1 * N + col + 1] = c[mt][nt][3] + bv1;
            }
        }
    }
}

// ==================================================================
// Fused flash attention with 3xBF16 mma, 64q x 64k tiles, 4 warps.
// Output written [pix][ch] into d_attn.
// ==================================================================
#define AS 72   // smem stride halves (bank = 4g+t, conflict-free)
__global__ __launch_bounds__(128, 3) void attn_mma(const float* __restrict__ q,
                                                   const float* __restrict__ kv,
                                                   float* __restrict__ outbuf) {
    extern __shared__ unsigned short smx[];
    unsigned short* Qh = smx;            // [64 q][72 d]
    unsigned short* Ql = Qh + 64 * AS;
    unsigned short* Kh = Ql + 64 * AS;   // [64 key][72 d]
    unsigned short* Kl = Kh + 64 * AS;
    unsigned short* Vh = Kl + 64 * AS;   // [64 d][72 key]
    unsigned short* Vl = Vh + 64 * AS;
    const int qb = blockIdx.x * 64, h = blockIdx.y, b = blockIdx.z;
    const int tid = threadIdx.x, lane = tid & 31, wid = tid >> 5;
    const int g = lane >> 2, tq = lane & 3;
    const float* qptr = q + ((size_t)(b * DIM + h * DH)) * HWQ + qb;
    const float* kptr = kv + ((size_t)(b * 2 * DIM + h * DH)) * LO;
    const float* vptr = kv + ((size_t)(b * 2 * DIM + DIM + h * DH)) * LO;

    // stage Q (transpose to [q][d], pre-scaled, split)
    for (int i = tid; i < 4096; i += 128) {
        int d = i >> 6, qq = i & 63;
        float v = qptr[(size_t)d * HWQ + qq] * SCALE;
        unsigned short hh, ll; split1(v, hh, ll);
        Qh[qq * AS + d] = hh; Ql[qq * AS + d] = ll;
    }
    __syncthreads();
    uint32_t qfh[4][4], qfl[4][4];
    const int r0 = wid * 16;
    #pragma unroll
    for (int kc = 0; kc < 4; kc++) {
        qfh[kc][0] = *(const uint32_t*)&Qh[(r0 + g) * AS + kc * 16 + 2 * tq];
        qfh[kc][1] = *(const uint32_t*)&Qh[(r0 + 8 + g) * AS + kc * 16 + 2 * tq];
        qfh[kc][2] = *(const uint32_t*)&Qh[(r0 + g) * AS + kc * 16 + 2 * tq + 8];
        qfh[kc][3] = *(const uint32_t*)&Qh[(r0 + 8 + g) * AS + kc * 16 + 2 * tq + 8];
        qfl[kc][0] = *(const uint32_t*)&Ql[(r0 + g) * AS + kc * 16 + 2 * tq];
        qfl[kc][1] = *(const uint32_t*)&Ql[(r0 + 8 + g) * AS + kc * 16 + 2 * tq];
        qfl[kc][2] = *(const uint32_t*)&Ql[(r0 + g) * AS + kc * 16 + 2 * tq + 8];
        qfl[kc][3] = *(const uint32_t*)&Ql[(r0 + 8 + g) * AS + kc * 16 + 2 * tq + 8];
    }

    float o[8][4];
    #pragma unroll
    for (int j = 0; j < 8; j++)
        #pragma unroll
        for (int k = 0; k < 4; k++) o[j][k] = 0.f;
    float mrow0 = -1e30f, mrow1 = -1e30f, lrow0 = 0.f, lrow1 = 0.f;

    for (int t = 0; t < 13; t++) {
        __syncthreads();
        for (int i = tid; i < 4096; i += 128) {
            int d = i >> 6, kk = i & 63, key = t * 64 + kk;
            float kvv = (key < LO) ? kptr[(size_t)d * LO + key] : 0.f;
            float vvv = (key < LO) ? vptr[(size_t)d * LO + key] : 0.f;
            unsigned short hh, ll;
            split1(kvv, hh, ll); Kh[kk * AS + d] = hh; Kl[kk * AS + d] = ll;
            split1(vvv, hh, ll); Vh[d * AS + kk] = hh; Vl[d * AS + kk] = ll;
        }
        __syncthreads();

        float s[8][4];
        #pragma unroll
        for (int j = 0; j < 8; j++)
            #pragma unroll
            for (int k = 0; k < 4; k++) s[j][k] = 0.f;
        #pragma unroll
        for (int kc = 0; kc < 4; kc++) {
            #pragma unroll
            for (int nt = 0; nt < 8; nt++) {
                uint32_t bh[2], bl[2];
                bh[0] = *(const uint32_t*)&Kh[(nt * 8 + g) * AS + kc * 16 + 2 * tq];
                bh[1] = *(const uint32_t*)&Kh[(nt * 8 + g) * AS + kc * 16 + 2 * tq + 8];
                bl[0] = *(const uint32_t*)&Kl[(nt * 8 + g) * AS + kc * 16 + 2 * tq];
                bl[1] = *(const uint32_t*)&Kl[(nt * 8 + g) * AS + kc * 16 + 2 * tq + 8];
                mma_bf16(s[nt], qfh[kc], bh);
                mma_bf16(s[nt], qfl[kc], bh);
                mma_bf16(s[nt], qfh[kc], bl);
            }
        }
        if (t == 12) {
            #pragma unroll
            for (int nt = 0; nt < 8; nt++) {
                int key0 = 768 + nt * 8 + 2 * tq;
                if (key0 >= LO) { s[nt][0] = s[nt][1] = s[nt][2] = s[nt][3] = -1e30f; }
            }
        }
        // online softmax (rows g, g+8)
        float mx0 = -1e30f, mx1 = -1e30f;
        #pragma unroll
        for (int nt = 0; nt < 8; nt++) {
            mx0 = fmaxf(mx0, fmaxf(s[nt][0], s[nt][1]));
            mx1 = fmaxf(mx1, fmaxf(s[nt][2], s[nt][3]));
        }
        mx0 = fmaxf(mx0, __shfl_xor_sync(0xffffffffu, mx0, 1));
        mx0 = fmaxf(mx0, __shfl_xor_sync(0xffffffffu, mx0, 2));
        mx1 = fmaxf(mx1, __shfl_xor_sync(0xffffffffu, mx1, 1));
        mx1 = fmaxf(mx1, __shfl_xor_sync(0xffffffffu, mx1, 2));
        float nm0 = fmaxf(mrow0, mx0), nm1 = fmaxf(mrow1, mx1);
        float corr0 = __expf(mrow0 - nm0), corr1 = __expf(mrow1 - nm1);
        mrow0 = nm0; mrow1 = nm1;
        float ps0 = 0.f, ps1 = 0.f;
        #pragma unroll
        for (int nt = 0; nt < 8; nt++) {
            s[nt][0] = __expf(s[nt][0] - nm0); ps0 += s[nt][0];
            s[nt][1] = __expf(s[nt][1] - nm0); ps0 += s[nt][1];
            s[nt][2] = __expf(s[nt][2] - nm1); ps1 += s[nt][2];
            s[nt][3] = __expf(s[nt][3] - nm1); ps1 += s[nt][3];
        }
        ps0 += __shfl_xor_sync(0xffffffffu, ps0, 1);
        ps0 += __shfl_xor_sync(0xffffffffu, ps0, 2);
        ps1 += __shfl_xor_sync(0xffffffffu, ps1, 1);
        ps1 += __shfl_xor_sync(0xffffffffu, ps1, 2);
        lrow0 = lrow0 * corr0 + ps0;
        lrow1 = lrow1 * corr1 + ps1;
        #pragma unroll
        for (int nt = 0; nt < 8; nt++) {
            o[nt][0] *= corr0; o[nt][1] *= corr0;
            o[nt][2] *= corr1; o[nt][3] *= corr1;
        }
        // P fragments (register permutation of S fragment) + PV mma
        uint32_t ph[4][4], pl[4][4];
        #pragma unroll
        for (int kc = 0; kc < 4; kc++) {
            split_pack(s[2 * kc][0],     s[2 * kc][1],     ph[kc][0], pl[kc][0]);
            split_pack(s[2 * kc][2],     s[2 * kc][3],     ph[kc][1], pl[kc][1]);
            split_pack(s[2 * kc + 1][0], s[2 * kc + 1][1], ph[kc][2], pl[kc][2]);
            split_pack(s[2 * kc + 1][2], s[2 * kc + 1][3], ph[kc][3], pl[kc][3]);
        }
        #pragma unroll
        for (int kc = 0; kc < 4; kc++) {
            #pragma unroll
            for (int nt = 0; nt < 8; nt++) {
                uint32_t vh2[2], vl2[2];
                vh2[0] = *(const uint32_t*)&Vh[(nt * 8 + g) * AS + kc * 16 + 2 * tq];
                vh2[1] = *(const uint32_t*)&Vh[(nt * 8 + g) * AS + kc * 16 + 2 * tq + 8];
                vl2[0] = *(const uint32_t*)&Vl[(nt * 8 + g) * AS + kc * 16 + 2 * tq];
                vl2[1] = *(const uint32_t*)&Vl[(nt * 8 + g) * AS + kc * 16 + 2 * tq + 8];
                mma_bf16(o[nt], ph[kc], vh2);
                mma_bf16(o[nt], pl[kc], vh2);
                mma_bf16(o[nt], ph[kc], vl2);
            }
        }
    }
    float inv0 = 1.f / lrow0, inv1 = 1.f / lrow1;
    float* ob = outbuf + ((size_t)b * HWQ + qb) * DIM + h * DH;
    int rlo = wid * 16 + g, rhi = rlo + 8;
    #pragma unroll
    for (int nt = 0; nt < 8; nt++) {
        int d = nt * 8 + 2 * tq;
        *(float2*)&ob[(size_t)rlo * DIM + d] = make_float2(o[nt][0] * inv0, o[nt][1] * inv0);
        *(float2*)&ob[(size_t)rhi * DIM + d] = make_float2(o[nt][2] * inv1, o[nt][3] * inv1);
    }
}

// ---------------- depthwise 5x5 s2 + bias + BN + exact GELU ----------------
__global__ void dw_bn_gelu_kernel(const float* __restrict__ q,
                                  const float* __restrict__ dw_w, const float* __restrict__ dw_b,
                                  const float* __restrict__ bn_w, const float* __restrict__ bn_b,
                                  const float* __restrict__ bn_mean, const float* __restrict__ bn_var,
                                  float* __restrict__ off) {
    int idx = blockIdx.x * blockDim.x + threadIdx.x;
    const int TOT = BSZ * GRP * NGD * LO;
    if (idx >= TOT) return;
    int pix = idx % LO;
    int c   = (idx / LO) % NGD;
    int n   = idx / (LO * NGD);
    int oy = pix / WO, ox = pix % WO;
    int b = n / GRP, g = n % GRP;
    const float* plane = q + ((size_t)(b * DIM + g * NGD + c)) * HWQ;
    const float* wk = dw_w + c * 25;
    float s = 0.f;
    #pragma unroll
    for (int ky = 0; ky < 5; ky++) {
        int iy = oy * 2 + ky - 2;
        if (iy < 0 || iy >= HH) continue;
        #pragma unroll
        for (int kx = 0; kx < 5; kx++) {
            int ix = ox * 2 + kx - 2;
            if (ix >= 0 && ix < WW) s = fmaf(plane[iy * WW + ix], wk[ky * 5 + kx], s);
        }
    }
    s += dw_b[c];
    s = (s - bn_mean[c]) * (bn_w[c] * rsqrtf(bn_var[c] + 1e-6f)) + bn_b[c];
    s = 0.5f * s * (1.0f + erff(s * 0.70710678118654752f));
    off[idx] = s;
}

// ---------------- pointwise 128->3 + offset/grid math ----------------
__global__ void pw_grid_kernel(const float* __restrict__ off, const float* __restrict__ pw_w,
                               float4* __restrict__ grid4) {
    int idx = blockIdx.x * blockDim.x + threadIdx.x;
    const int TOT = BSZ * GRP * LO;
    if (idx >= TOT) return;
    int n = idx / LO, pix = idx % LO;
    const float* base = off + (size_t)n * NGD * LO + pix;
    float o0 = 0.f, o1 = 0.f, o2 = 0.f;
    #pragma unroll 4
    for (int c = 0; c < NGD; c++) {
        float v = base[(size_t)c * LO];
        o0 = fmaf(v, pw_w[c], o0);
        o1 = fmaf(v, pw_w[NGD + c], o1);
        o2 = fmaf(v, pw_w[2 * NGD + c], o2);
    }
    int oy = pix / WO, ox = pix % WO;
    float ry = ((0.5f + (float)oy) / (float)HO) * 2.f - 1.f;
    float rx = ((0.5f + (float)ox) / (float)WO) * 2.f - 1.f;
    float posy = tanhf(o0) * (2.0f / (float)HO) + ry;
    float posx = tanhf(o1) * (2.0f / (float)WO) + rx;
    float gx = (posx + 1.f) * 0.5f * (float)(WW - 1);
    float gy = (posy + 1.f) * 0.5f * (float)(HH - 1);
    float sig = 1.f / (1.f + expf(-o2));
    float mod = 1.f / (1.f + expf(-sig));
    grid4[idx] = make_float4(gx, gy, mod, 0.f);
}

// ---------------- bilinear grid sample * modulation ----------------
__global__ void sample_kernel(const float* __restrict__ x, const float4* __restrict__ grid4,
                              float* __restrict__ xs) {
    int nc = blockIdx.x;
    int pix = blockIdx.y * blockDim.x + threadIdx.x;
    if (pix >= LO) return;
    int c = nc & (NGD - 1), n = nc >> 7;
    int b = n / GRP, g = n % GRP;
    float4 gq = grid4[(size_t)n * LO + pix];
    float gx = gq.x, gy = gq.y, mod = gq.z;
    float x0f = floorf(gx), y0f = floorf(gy);
    float x1f = x0f + 1.f, y1f = y0f + 1.f;
    const float* plane = x + ((size_t)(b * DIM + g * NGD + c)) * HWQ;

    float t00 = 0.f, t01 = 0.f, t10 = 0.f, t11 = 0.f;
    bool vx0 = (x0f >= 0.f) && (x0f <= (float)(WW - 1));
    bool vx1 = (x1f >= 0.f) && (x1f <= (float)(WW - 1));
    bool vy0 = (y0f >= 0.f) && (y0f <= (float)(HH - 1));
    bool vy1 = (y1f >= 0.f) && (y1f <= (float)(HH - 1));
    int xi0 = (int)fminf(fmaxf(x0f, 0.f), (float)(WW - 1));
    int xi1 = (int)fminf(fmaxf(x1f, 0.f), (float)(WW - 1));
    int yi0 = (int)fminf(fmaxf(y0f, 0.f), (float)(HH - 1));
    int yi1 = (int)fminf(fmaxf(y1f, 0.f), (float)(HH - 1));
    if (vy0 && vx0) t00 = plane[yi0 * WW + xi0];
    if (vy1 && vx0) t10 = plane[yi1 * WW + xi0];
    if (vy0 && vx1) t01 = plane[yi0 * WW + xi1];
    if (vy1 && vx1) t11 = plane[yi1 * WW + xi1];

    float v = t00 * (x1f - gx) * (y1f - gy)
            + t10 * (x1f - gx) * (gy - y0f)
            + t01 * (gx - x0f) * (y1f - gy)
            + t11 * (gx - x0f) * (gy - y0f);
    xs[((size_t)(b * DIM + g * NGD + c)) * LO + pix] = v * mod;
}

// ---------------- launch ----------------
extern "C" void kernel_launch(void* const* d_in, const int* in_sizes, int n_in,
                              void* d_out, int out_size) {
    const float* x      = (const float*)d_in[0];
    const float* q_w    = (const float*)d_in[1];
    const float* kv_w   = (const float*)d_in[2];
    const float* proj_w = (const float*)d_in[3];
    const float* proj_b = (const float*)d_in[4];
    const float* dw_w   = (const float*)d_in[5];
    const float* dw_b   = (const float*)d_in[6];
    const float* bn_w   = (const float*)d_in[7];
    const float* bn_b   = (const float*)d_in[8];
    const float* bn_mean= (const float*)d_in[9];
    const float* bn_var = (const float*)d_in[10];
    const float* pw_w   = (const float*)d_in[11];
    float* out = (float*)d_out;

    float *q, *off, *xs, *kvb, *attn; float4* grid;
    cudaGetSymbolAddress((void**)&q,    d_q);
    cudaGetSymbolAddress((void**)&off,  d_off);
    cudaGetSymbolAddress((void**)&grid, d_grid);
    cudaGetSymbolAddress((void**)&xs,   d_xs);
    cudaGetSymbolAddress((void**)&kvb,  d_kv);
    cudaGetSymbolAddress((void**)&attn, d_attn);

    // K1: q = q_w @ x
    {
        dim3 g1((HWQ + 127) / 128, DIM / 128, BSZ);
        gemm_mma<false><<<g1, 256>>>(q_w, x, q, nullptr, DIM, HWQ);
    }
    // K2: depthwise conv + bias + BN + gelu
    {
        int tot = BSZ * GRP * NGD * LO;
        dw_bn_gelu_kernel<<<(tot + 255) / 256, 256>>>(q, dw_w, dw_b, bn_w, bn_b,
                                                      bn_mean, bn_var, off);
    }
    // K3a: pointwise + grid
    {
        int tot = BSZ * GRP * LO;
        pw_grid_kernel<<<(tot + 255) / 256, 256>>>(off, pw_w, grid);
    }
    // K3b: bilinear sampling
    {
        dim3 g((BSZ * GRP * NGD), (LO + 255) / 256);
        sample_kernel<<<g, 256>>>(x, grid, xs);
    }
    // K4: kv = kv_w @ xs
    {
        dim3 g((LO + 127) / 128, (2 * DIM) / 128, BSZ);
        gemm_mma<false><<<g, 256>>>(kv_w, xs, kvb, nullptr, 2 * DIM, LO);
    }
    // K5: fused attention -> d_attn [pix][ch]
    {
        dim3 g(HWQ / 64, NH, BSZ);
        size_t smem = (size_t)6 * 64 * AS * sizeof(unsigned short);  // 55296 B
        cudaFuncSetAttribute(attn_mma, cudaFuncAttributeMaxDynamicSharedMemorySize, (int)smem);
        attn_mma<<<g, 128, smem>>>(q, kvb, attn);
    }
    // K6: out = proj_w @ attn^T + proj_b  (attn is [pix][ch] => BT loader)
    {
        dim3 g1((HWQ + 127) / 128, DIM / 128, BSZ);
        gemm_mma<true><<<g1, 256>>>(proj_w, attn, out, proj_b, DIM, HWQ);
    }
}

// round 6
// speedup vs baseline: 2.9189x; 1.6845x over previous
#include <cuda_runtime.h>
#include <cuda_bf16.h>
#include <math.h>
#include <stdint.h>

// ---------------- problem constants ----------------
#define BSZ   8
#define DIM   384
#define HH    56
#define WW    56
#define HWQ   3136
#define NH    6
#define DH    64
#define GRP   3
#define NGD   128
#define HO    28
#define WO    28
#define LO    784
#define SCALE 0.125f

typedef unsigned short u16;

// ---------------- scratch (device globals, no allocs) ----------------
__device__ float  d_q  [(size_t)BSZ * DIM * HWQ];      // f32 q (dw conv input)
__device__ u16    d_qh [(size_t)BSZ * DIM * HWQ];      // q split (attention Q)
__device__ u16    d_ql [(size_t)BSZ * DIM * HWQ];
__device__ u16    d_xh [(size_t)BSZ * DIM * HWQ];      // x split (q GEMM B)
__device__ u16    d_xl [(size_t)BSZ * DIM * HWQ];
__device__ u16    d_wqh[DIM * DIM],     d_wql[DIM * DIM];
__device__ u16    d_wkh[2 * DIM * DIM], d_wkl[2 * DIM * DIM];
__device__ u16    d_wph[DIM * DIM],     d_wpl[DIM * DIM];
__device__ float  d_off [(size_t)BSZ * GRP * NGD * LO];
__device__ float4 d_grid[(size_t)BSZ * GRP * LO];
__device__ u16    d_xsh[(size_t)BSZ * DIM * LO],     d_xsl[(size_t)BSZ * DIM * LO];
__device__ u16    d_kvh[(size_t)BSZ * 2 * DIM * LO], d_kvl[(size_t)BSZ * 2 * DIM * LO];
__device__ u16    d_ah [(size_t)BSZ * HWQ * DIM],    d_al [(size_t)BSZ * HWQ * DIM];

// ---------------- helpers ----------------
__device__ __forceinline__ void split1(float x, u16& h, u16& l) {
    __nv_bfloat16 bh = __float2bfloat16(x);
    float r = x - __bfloat162float(bh);
    __nv_bfloat16 bl = __float2bfloat16(r);
    h = __bfloat16_as_ushort(bh);
    l = __bfloat16_as_ushort(bl);
}
__device__ __forceinline__ void split_pack(float x, float y, uint32_t& ph, uint32_t& pl) {
    u16 xh, xl, yh, yl;
    split1(x, xh, xl); split1(y, yh, yl);
    ph = ((uint32_t)yh << 16) | xh;
    pl = ((uint32_t)yl << 16) | xl;
}
__device__ __forceinline__ void mma_bf16(float* c, const uint32_t* a, const uint32_t* b) {
    asm volatile(
        "mma.sync.aligned.m16n8k16.row.col.f32.bf16.bf16.f32 "
        "{%0,%1,%2,%3}, {%4,%5,%6,%7}, {%8,%9}, {%0,%1,%2,%3};\n"
        : "+f"(c[0]), "+f"(c[1]), "+f"(c[2]), "+f"(c[3])
        : "r"(a[0]), "r"(a[1]), "r"(a[2]), "r"(a[3]), "r"(b[0]), "r"(b[1]));
}
__device__ __forceinline__ void ldsm4(uint32_t* r, const u16* p) {
    uint32_t a = (uint32_t)__cvta_generic_to_shared(p);
    asm volatile("ldmatrix.sync.aligned.m8n8.x4.shared.b16 {%0,%1,%2,%3}, [%4];"
                 : "=r"(r[0]), "=r"(r[1]), "=r"(r[2]), "=r"(r[3]) : "r"(a));
}
__device__ __forceinline__ void ldsm4t(uint32_t* r, const u16* p) {
    uint32_t a = (uint32_t)__cvta_generic_to_shared(p);
    asm volatile("ldmatrix.sync.aligned.m8n8.x4.trans.shared.b16 {%0,%1,%2,%3}, [%4];"
                 : "=r"(r[0]), "=r"(r[1]), "=r"(r[2]), "=r"(r[3]) : "r"(a));
}

// ---------------- f32 -> (hi,lo) bf16 split, vectorized ----------------
__global__ void split_kernel(const float* __restrict__ src, u16* __restrict__ h,
                             u16* __restrict__ l, int n4) {
    int i = blockIdx.x * blockDim.x + threadIdx.x;
    if (i >= n4) return;
    float4 v = ((const float4*)src)[i];
    ushort4 hh, ll;
    split1(v.x, hh.x, ll.x); split1(v.y, hh.y, ll.y);
    split1(v.z, hh.z, ll.z); split1(v.w, hh.w, ll.w);
    ((ushort4*)h)[i] = hh; ((ushort4*)l)[i] = ll;
}

// ==================================================================
// GEMM: Y[b] = W(MxK=384) @ X[b](384xN), pre-split bf16 operands.
// BT=false: X [K][N]; BT=true: X [N][K].
// ==================================================================
#define SST 24
#define BNS 136
template<bool BT, bool WF32, bool WSPLIT>
__global__ __launch_bounds__(256, 2) void gemm_bf16(
    const u16* __restrict__ Wh, const u16* __restrict__ Wl,
    const u16* __restrict__ Xh, const u16* __restrict__ Xl,
    float* __restrict__ Yf, u16* __restrict__ Ysh, u16* __restrict__ Ysl,
    const float* __restrict__ bias, int M, int N) {
    const int KD = 384;
    __shared__ __align__(16) u16 Ah[128 * SST], Al[128 * SST];
    __shared__ __align__(16) u16 Bhs[128 * SST], Bls[128 * SST];
    const int bz = blockIdx.z;
    const size_t xoff = (size_t)bz * KD * N;
    const int m0 = blockIdx.y * 128, n0 = blockIdx.x * 128;
    const int tid = threadIdx.x, lane = tid & 31, wid = tid >> 5;
    const int wm = wid & 3, wn = wid >> 2;
    float c[2][8][4] = {};

    const int arow = tid >> 1, acol = (tid & 1) * 8;
    const int bro = tid >> 4, bcol = (tid & 15) * 8;   // NN
    const int bn2 = tid >> 1, bk2 = (tid & 1) * 8;     // BT
    uint4 rAh, rAl, rBh, rBl;
    const uint4 z4 = make_uint4(0, 0, 0, 0);

    auto LOAD = [&](int kc) {
        size_t ao = (size_t)(m0 + arow) * KD + kc * 16 + acol;
        rAh = *(const uint4*)&Wh[ao];
        rAl = *(const uint4*)&Wl[ao];
        if (!BT) {
            bool v = (n0 + bcol) < N;
            size_t o = xoff + (size_t)(kc * 16 + bro) * N + n0 + bcol;
            rBh = v ? *(const uint4*)&Xh[o] : z4;
            rBl = v ? *(const uint4*)&Xl[o] : z4;
        } else {
            bool v = (n0 + bn2) < N;
            size_t o = xoff + (size_t)(n0 + bn2) * KD + kc * 16 + bk2;
            rBh = v ? *(const uint4*)&Xh[o] : z4;
            rBl = v ? *(const uint4*)&Xl[o] : z4;
        }
    };
    auto STORE = [&]() {
        *(uint4*)&Ah[arow * SST + acol] = rAh;
        *(uint4*)&Al[arow * SST + acol] = rAl;
        if (!BT) {
            *(uint4*)&Bhs[bro * BNS + bcol] = rBh;
            *(uint4*)&Bls[bro * BNS + bcol] = rBl;
        } else {
            *(uint4*)&Bhs[bn2 * SST + bk2] = rBh;
            *(uint4*)&Bls[bn2 * SST + bk2] = rBl;
        }
    };

    LOAD(0); STORE();
    const int afr = wm * 32 + (lane & 15);
    const int afc = (lane >> 4) << 3;
    for (int kc = 0; kc < 24; kc++) {
        __syncthreads();
        if (kc < 23) LOAD(kc + 1);
        uint32_t ah[2][4], al[2][4];
        #pragma unroll
        for (int mt = 0; mt < 2; mt++) {
            ldsm4(ah[mt], &Ah[(afr + mt * 16) * SST + afc]);
            ldsm4(al[mt], &Al[(afr + mt * 16) * SST + afc]);
        }
        #pragma unroll
        for (int p = 0; p < 4; p++) {
            uint32_t bh4[4], bl4[4];
            if (!BT) {
                int r = lane & 15, cN = wn * 64 + p * 16 + afc;
                ldsm4t(bh4, &Bhs[r * BNS + cN]);
                ldsm4t(bl4, &Bls[r * BNS + cN]);
            } else {
                int r = wn * 64 + p * 16 + (lane & 7) + afc;
                int cK = ((lane >> 3) & 1) << 3;
                ldsm4(bh4, &Bhs[r * SST + cK]);
                ldsm4(bl4, &Bls[r * SST + cK]);
            }
            #pragma unroll
            for (int sub = 0; sub < 2; sub++) {
                int nt = 2 * p + sub;
                #pragma unroll
                for (int mt = 0; mt < 2; mt++) {
                    mma_bf16(c[mt][nt], ah[mt], &bh4[2 * sub]);
                    mma_bf16(c[mt][nt], al[mt], &bh4[2 * sub]);
                    mma_bf16(c[mt][nt], ah[mt], &bl4[2 * sub]);
                }
            }
        }
        __syncthreads();
        if (kc < 23) STORE();
    }

    const int g = lane >> 2, tq = lane & 3;
    #pragma unroll
    for (int mt = 0; mt < 2; mt++) {
        int row0 = m0 + wm * 32 + mt * 16 + g;
        int row1 = row0 + 8;
        float bv0 = bias ? bias[row0] : 0.f;
        float bv1 = bias ? bias[row1] : 0.f;
        #pragma unroll
        for (int nt = 0; nt < 8; nt++) {
            int col = n0 + wn * 64 + nt * 8 + 2 * tq;
            if (col < N) {
                float v00 = c[mt][nt][0] + bv0, v01 = c[mt][nt][1] + bv0;
                float v10 = c[mt][nt][2] + bv1, v11 = c[mt][nt][3] + bv1;
                size_t o0 = (size_t)bz * M * N + (size_t)row0 * N + col;
                size_t o1 = (size_t)bz * M * N + (size_t)row1 * N + col;
                if (WF32) {
                    *(float2*)&Yf[o0] = make_float2(v00, v01);
                    *(float2*)&Yf[o1] = make_float2(v10, v11);
                }
                if (WSPLIT) {
                    u16 h0, l0, h1, l1;
                    split1(v00, h0, l0); split1(v01, h1, l1);
                    *(uint32_t*)&Ysh[o0] = ((uint32_t)h1 << 16) | h0;
                    *(uint32_t*)&Ysl[o0] = ((uint32_t)l1 << 16) | l0;
                    split1(v10, h0, l0); split1(v11, h1, l1);
                    *(uint32_t*)&Ysh[o1] = ((uint32_t)h1 << 16) | h0;
                    *(uint32_t*)&Ysl[o1] = ((uint32_t)l1 << 16) | l0;
                }
            }
        }
    }
}

// ==================================================================
// Fused flash attention, pre-split operands + ldmatrix fragments.
// ==================================================================
#define AS 72
__global__ __launch_bounds__(128, 3) void attn_bf16(
    const u16* __restrict__ qh, const u16* __restrict__ ql,
    const u16* __restrict__ kvh, const u16* __restrict__ kvl,
    u16* __restrict__ oh, u16* __restrict__ ol) {
    extern __shared__ __align__(16) u16 smx[];
    u16* Qh = smx;
    u16* Ql = Qh + 64 * AS;
    u16* Kh = Ql + 64 * AS;   // [d][key]
    u16* Kl = Kh + 64 * AS;
    u16* Vh = Kl + 64 * AS;   // [d][key]
    u16* Vl = Vh + 64 * AS;
    const int qb = blockIdx.x * 64, h = blockIdx.y, b = blockIdx.z;
    const int tid = threadIdx.x, lane = tid & 31, wid = tid >> 5;
    const int g = lane >> 2, tq = lane & 3;
    const size_t qoff = ((size_t)(b * DIM + h * DH)) * HWQ + qb;
    const size_t koff = ((size_t)(b * 2 * DIM + h * DH)) * LO;
    const size_t voff = ((size_t)(b * 2 * DIM + DIM + h * DH)) * LO;

    // stage Q [q][d]
    for (int i = tid; i < 4096; i += 128) {
        int d = i >> 6, qq = i & 63;
        Qh[qq * AS + d] = qh[qoff + (size_t)d * HWQ + qq];
        Ql[qq * AS + d] = ql[qoff + (size_t)d * HWQ + qq];
    }
    __syncthreads();
    uint32_t qfh[4][4], qfl[4][4];
    const int afr = wid * 16 + (lane & 15);
    const int afc = (lane >> 4) << 3;
    #pragma unroll
    for (int kc = 0; kc < 4; kc++) {
        ldsm4(qfh[kc], &Qh[afr * AS + kc * 16 + afc]);
        ldsm4(qfl[kc], &Ql[afr * AS + kc * 16 + afc]);
    }

    float o[8][4] = {};
    float mrow0 = -1e30f, mrow1 = -1e30f, lrow0 = 0.f, lrow1 = 0.f;
    const uint4 z4 = make_uint4(0, 0, 0, 0);

    for (int t = 0; t < 13; t++) {
        __syncthreads();
        for (int i = tid; i < 512; i += 128) {
            int d = i >> 3, c8 = (i & 7) * 8;
            int key = t * 64 + c8;
            bool v = key < LO;
            size_t gk = koff + (size_t)d * LO + key;
            size_t gv = voff + (size_t)d * LO + key;
            uint4 a  = v ? *(const uint4*)&kvh[gk] : z4;
            uint4 bb = v ? *(const uint4*)&kvl[gk] : z4;
            uint4 cc = v ? *(const uint4*)&kvh[gv] : z4;
            uint4 dd = v ? *(const uint4*)&kvl[gv] : z4;
            *(uint4*)&Kh[d * AS + c8] = a;
            *(uint4*)&Kl[d * AS + c8] = bb;
            *(uint4*)&Vh[d * AS + c8] = cc;
            *(uint4*)&Vl[d * AS + c8] = dd;
        }
        __syncthreads();

        float s[8][4] = {};
        #pragma unroll
        for (int kc = 0; kc < 4; kc++) {
            #pragma unroll
            for (int p = 0; p < 4; p++) {
                uint32_t bh4[4], bl4[4];
                int r = kc * 16 + (lane & 15), cN = p * 16 + afc;
                ldsm4t(bh4, &Kh[r * AS + cN]);
                ldsm4t(bl4, &Kl[r * AS + cN]);
                #pragma unroll
                for (int sub = 0; sub < 2; sub++) {
                    int nt = 2 * p + sub;
                    mma_bf16(s[nt], qfh[kc], &bh4[2 * sub]);
                    mma_bf16(s[nt], qfl[kc], &bh4[2 * sub]);
                    mma_bf16(s[nt], qfh[kc], &bl4[2 * sub]);
                }
            }
        }
        #pragma unroll
        for (int nt = 0; nt < 8; nt++) {
            s[nt][0] *= SCALE; s[nt][1] *= SCALE;
            s[nt][2] *= SCALE; s[nt][3] *= SCALE;
        }
        if (t == 12) {
            #pragma unroll
            for (int nt = 0; nt < 8; nt++) {
                int key0 = 768 + nt * 8 + 2 * tq;
                if (key0 >= LO) { s[nt][0] = s[nt][1] = s[nt][2] = s[nt][3] = -1e30f; }
            }
        }
        // online softmax (rows g, g+8)
        float mx0 = -1e30f, mx1 = -1e30f;
        #pragma unroll
        for (int nt = 0; nt < 8; nt++) {
            mx0 = fmaxf(mx0, fmaxf(s[nt][0], s[nt][1]));
            mx1 = fmaxf(mx1, fmaxf(s[nt][2], s[nt][3]));
        }
        mx0 = fmaxf(mx0, __shfl_xor_sync(0xffffffffu, mx0, 1));
        mx0 = fmaxf(mx0, __shfl_xor_sync(0xffffffffu, mx0, 2));
        mx1 = fmaxf(mx1, __shfl_xor_sync(0xffffffffu, mx1, 1));
        mx1 = fmaxf(mx1, __shfl_xor_sync(0xffffffffu, mx1, 2));
        float nm0 = fmaxf(mrow0, mx0), nm1 = fmaxf(mrow1, mx1);
        float corr0 = __expf(mrow0 - nm0), corr1 = __expf(mrow1 - nm1);
        mrow0 = nm0; mrow1 = nm1;
        float ps0 = 0.f, ps1 = 0.f;
        #pragma unroll
        for (int nt = 0; nt < 8; nt++) {
            s[nt][0] = __expf(s[nt][0] - nm0); ps0 += s[nt][0];
            s[nt][1] = __expf(s[nt][1] - nm0); ps0 += s[nt][1];
            s[nt][2] = __expf(s[nt][2] - nm1); ps1 += s[nt][2];
            s[nt][3] = __expf(s[nt][3] - nm1); ps1 += s[nt][3];
        }
        ps0 += __shfl_xor_sync(0xffffffffu, ps0, 1);
        ps0 += __shfl_xor_sync(0xffffffffu, ps0, 2);
        ps1 += __shfl_xor_sync(0xffffffffu, ps1, 1);
        ps1 += __shfl_xor_sync(0xffffffffu, ps1, 2);
        lrow0 = lrow0 * corr0 + ps0;
        lrow1 = lrow1 * corr1 + ps1;
        #pragma unroll
        for (int nt = 0; nt < 8; nt++) {
            o[nt][0] *= corr0; o[nt][1] *= corr0;
            o[nt][2] *= corr1; o[nt][3] *= corr1;
        }
        // P fragments (register permutation of S) + PV mma
        uint32_t ph[4][4], pl[4][4];
        #pragma unroll
        for (int kc = 0; kc < 4; kc++) {
            split_pack(s[2 * kc][0],     s[2 * kc][1],     ph[kc][0], pl[kc][0]);
            split_pack(s[2 * kc][2],     s[2 * kc][3],     ph[kc][1], pl[kc][1]);
            split_pack(s[2 * kc + 1][0], s[2 * kc + 1][1], ph[kc][2], pl[kc][2]);
            split_pack(s[2 * kc + 1][2], s[2 * kc + 1][3], ph[kc][3], pl[kc][3]);
        }
        #pragma unroll
        for (int kc = 0; kc < 4; kc++) {
            #pragma unroll
            for (int p = 0; p < 4; p++) {
                uint32_t vh4[4], vl4[4];
                int vr = p * 16 + (lane & 7) + afc;
                int vc = kc * 16 + (((lane >> 3) & 1) << 3);
                ldsm4(vh4, &Vh[vr * AS + vc]);
                ldsm4(vl4, &Vl[vr * AS + vc]);
                #pragma unroll
                for (int sub = 0; sub < 2; sub++) {
                    int nt = 2 * p + sub;
                    mma_bf16(o[nt], ph[kc], &vh4[2 * sub]);
                    mma_bf16(o[nt], pl[kc], &vh4[2 * sub]);
                    mma_bf16(o[nt], ph[kc], &vl4[2 * sub]);
                }
            }
        }
    }
    float inv0 = 1.f / lrow0, inv1 = 1.f / lrow1;
    size_t base = (size_t)b * HWQ + qb;
    int rlo = wid * 16 + g, rhi = rlo + 8;
    #pragma unroll
    for (int nt = 0; nt < 8; nt++) {
        int d = h * DH + nt * 8 + 2 * tq;
        u16 h0, l0, h1, l1;
        split1(o[nt][0] * inv0, h0, l0); split1(o[nt][1] * inv0, h1, l1);
        *(uint32_t*)&oh[(base + rlo) * DIM + d] = ((uint32_t)h1 << 16) | h0;
        *(uint32_t*)&ol[(base + rlo) * DIM + d] = ((uint32_t)l1 << 16) | l0;
        split1(o[nt][2] * inv1, h0, l0); split1(o[nt][3] * inv1, h1, l1);
        *(uint32_t*)&oh[(base + rhi) * DIM + d] = ((uint32_t)h1 << 16) | h0;
        *(uint32_t*)&ol[(base + rhi) * DIM + d] = ((uint32_t)l1 << 16) | l0;
    }
}

// ---------------- depthwise 5x5 s2 + bias + BN + exact GELU ----------------
__global__ void dw_bn_gelu_kernel(const float* __restrict__ q,
                                  const float* __restrict__ dw_w, const float* __restrict__ dw_b,
                                  const float* __restrict__ bn_w, const float* __restrict__ bn_b,
                                  const float* __restrict__ bn_mean, const float* __restrict__ bn_var,
                                  float* __restrict__ off) {
    int idx = blockIdx.x * blockDim.x + threadIdx.x;
    const int TOT = BSZ * GRP * NGD * LO;
    if (idx >= TOT) return;
    int pix = idx % LO;
    int c   = (idx / LO) % NGD;
    int n   = idx / (LO * NGD);
    int oy = pix / WO, ox = pix % WO;
    int b = n / GRP, g = n % GRP;
    const float* plane = q + ((size_t)(b * DIM + g * NGD + c)) * HWQ;
    const float* wk = dw_w + c * 25;
    float s = 0.f;
    #pragma unroll
    for (int ky = 0; ky < 5; ky++) {
        int iy = oy * 2 + ky - 2;
        if (iy < 0 || iy >= HH) continue;
        #pragma unroll
        for (int kx = 0; kx < 5; kx++) {
            int ix = ox * 2 + kx - 2;
            if (ix >= 0 && ix < WW) s = fmaf(plane[iy * WW + ix], wk[ky * 5 + kx], s);
        }
    }
    s += dw_b[c];
    s = (s - bn_mean[c]) * (bn_w[c] * rsqrtf(bn_var[c] + 1e-6f)) + bn_b[c];
    s = 0.5f * s * (1.0f + erff(s * 0.70710678118654752f));
    off[idx] = s;
}

// ---------------- pointwise 128->3 + offset/grid math ----------------
__global__ void pw_grid_kernel(const float* __restrict__ off, const float* __restrict__ pw_w,
                               float4* __restrict__ grid4) {
    int idx = blockIdx.x * blockDim.x + threadIdx.x;
    const int TOT = BSZ * GRP * LO;
    if (idx >= TOT) return;
    int n = idx / LO, pix = idx % LO;
    const float* base = off + (size_t)n * NGD * LO + pix;
    float o0 = 0.f, o1 = 0.f, o2 = 0.f;
    #pragma unroll 4
    for (int c = 0; c < NGD; c++) {
        float v = base[(size_t)c * LO];
        o0 = fmaf(v, pw_w[c], o0);
        o1 = fmaf(v, pw_w[NGD + c], o1);
        o2 = fmaf(v, pw_w[2 * NGD + c], o2);
    }
    int oy = pix / WO, ox = pix % WO;
    float ry = ((0.5f + (float)oy) / (float)HO) * 2.f - 1.f;
    float rx = ((0.5f + (float)ox) / (float)WO) * 2.f - 1.f;
    float posy = tanhf(o0) * (2.0f / (float)HO) + ry;
    float posx = tanhf(o1) * (2.0f / (float)WO) + rx;
    float gx = (posx + 1.f) * 0.5f * (float)(WW - 1);
    float gy = (posy + 1.f) * 0.5f * (float)(HH - 1);
    float sig = 1.f / (1.f + expf(-o2));
    float mod = 1.f / (1.f + expf(-sig));
    grid4[idx] = make_float4(gx, gy, mod, 0.f);
}

// ---------------- bilinear grid sample * modulation -> split bf16 ----------------
__global__ void sample_kernel(const float* __restrict__ x, const float4* __restrict__ grid4,
                              u16* __restrict__ xsh, u16* __restrict__ xsl) {
    int nc = blockIdx.x;
    int pix = blockIdx.y * blockDim.x + threadIdx.x;
    if (pix >= LO) return;
    int c = nc & (NGD - 1), n = nc >> 7;
    int b = n / GRP, g = n % GRP;
    float4 gq = grid4[(size_t)n * LO + pix];
    float gx = gq.x, gy = gq.y, mod = gq.z;
    float x0f = floorf(gx), y0f = floorf(gy);
    float x1f = x0f + 1.f, y1f = y0f + 1.f;
    const float* plane = x + ((size_t)(b * DIM + g * NGD + c)) * HWQ;

    float t00 = 0.f, t01 = 0.f, t10 = 0.f, t11 = 0.f;
    bool vx0 = (x0f >= 0.f) && (x0f <= (float)(WW - 1));
    bool vx1 = (x1f >= 0.f) && (x1f <= (float)(WW - 1));
    bool vy0 = (y0f >= 0.f) && (y0f <= (float)(HH - 1));
    bool vy1 = (y1f >= 0.f) && (y1f <= (float)(HH - 1));
    int xi0 = (int)fminf(fmaxf(x0f, 0.f), (float)(WW - 1));
    int xi1 = (int)fminf(fmaxf(x1f, 0.f), (float)(WW - 1));
    int yi0 = (int)fminf(fmaxf(y0f, 0.f), (float)(HH - 1));
    int yi1 = (int)fminf(fmaxf(y1f, 0.f), (float)(HH - 1));
    if (vy0 && vx0) t00 = plane[yi0 * WW + xi0];
    if (vy1 && vx0) t10 = plane[yi1 * WW + xi0];
    if (vy0 && vx1) t01 = plane[yi0 * WW + xi1];
    if (vy1 && vx1) t11 = plane[yi1 * WW + xi1];

    float v = t00 * (x1f - gx) * (y1f - gy)
            + t10 * (x1f - gx) * (gy - y0f)
            + t01 * (gx - x0f) * (y1f - gy)
            + t11 * (gx - x0f) * (gy - y0f);
    v *= mod;
    u16 hh, ll; split1(v, hh, ll);
    size_t o = ((size_t)(b * DIM + g * NGD + c)) * LO + pix;
    xsh[o] = hh; xsl[o] = ll;
}

// ---------------- launch ----------------
extern "C" void kernel_launch(void* const* d_in, const int* in_sizes, int n_in,
                              void* d_out, int out_size) {
    const float* x      = (const float*)d_in[0];
    const float* q_w    = (const float*)d_in[1];
    const float* kv_w   = (const float*)d_in[2];
    const float* proj_w = (const float*)d_in[3];
    const float* proj_b = (const float*)d_in[4];
    const float* dw_w   = (const float*)d_in[5];
    const float* dw_b   = (const float*)d_in[6];
    const float* bn_w   = (const float*)d_in[7];
    const float* bn_b   = (const float*)d_in[8];
    const float* bn_mean= (const float*)d_in[9];
    const float* bn_var = (const float*)d_in[10];
    const float* pw_w   = (const float*)d_in[11];
    float* out = (float*)d_out;

    float *q, *off; float4* grid;
    u16 *qh, *ql, *xh, *xl, *wqh, *wql, *wkh, *wkl, *wph, *wpl;
    u16 *xsh, *xsl, *kvh, *kvl, *ah, *al;
    cudaGetSymbolAddress((void**)&q,    d_q);
    cudaGetSymbolAddress((void**)&off,  d_off);
    cudaGetSymbolAddress((void**)&grid, d_grid);
    cudaGetSymbolAddress((void**)&qh,   d_qh);
    cudaGetSymbolAddress((void**)&ql,   d_ql);
    cudaGetSymbolAddress((void**)&xh,   d_xh);
    cudaGetSymbolAddress((void**)&xl,   d_xl);
    cudaGetSymbolAddress((void**)&wqh,  d_wqh);
    cudaGetSymbolAddress((void**)&wql,  d_wql);
    cudaGetSymbolAddress((void**)&wkh,  d_wkh);
    cudaGetSymbolAddress((void**)&wkl,  d_wkl);
    cudaGetSymbolAddress((void**)&wph,  d_wph);
    cudaGetSymbolAddress((void**)&wpl,  d_wpl);
    cudaGetSymbolAddress((void**)&xsh,  d_xsh);
    cudaGetSymbolAddress((void**)&xsl,  d_xsl);
    cudaGetSymbolAddress((void**)&kvh,  d_kvh);
    cudaGetSymbolAddress((void**)&kvl,  d_kvl);
    cudaGetSymbolAddress((void**)&ah,   d_ah);
    cudaGetSymbolAddress((void**)&al,   d_al);

    // pre-split x and weights
    {
        int n4 = BSZ * DIM * HWQ / 4;
        split_kernel<<<(n4 + 255) / 256, 256>>>(x, xh, xl, n4);
        int w4 = DIM * DIM / 4;
        split_kernel<<<(w4 + 255) / 256, 256>>>(q_w, wqh, wql, w4);
        split_kernel<<<(2 * w4 + 255) / 256, 256>>>(kv_w, wkh, wkl, 2 * w4);
        split_kernel<<<(w4 + 255) / 256, 256>>>(proj_w, wph, wpl, w4);
    }
    // K1: q = q_w @ x  -> f32 + split
    {
        dim3 g1((HWQ + 127) / 128, DIM / 128, BSZ);
        gemm_bf16<false, true, true><<<g1, 256>>>(wqh, wql, xh, xl, q, qh, ql,
                                                  nullptr, DIM, HWQ);
    }
    // K2: depthwise conv + bias + BN + gelu
    {
        int tot = BSZ * GRP * NGD * LO;
        dw_bn_gelu_kernel<<<(tot + 255) / 256, 256>>>(q, dw_w, dw_b, bn_w, bn_b,
                                                      bn_mean, bn_var, off);
    }
    // K3a: pointwise + grid
    {
        int tot = BSZ * GRP * LO;
        pw_grid_kernel<<<(tot + 255) / 256, 256>>>(off, pw_w, grid);
    }
    // K3b: bilinear sampling -> xs split
    {
        dim3 g((BSZ * GRP * NGD), (LO + 255) / 256);
        sample_kernel<<<g, 256>>>(x, grid, xsh, xsl);
    }
    // K4: kv = kv_w @ xs -> split only
    {
        dim3 g((LO + 127) / 128, (2 * DIM) / 128, BSZ);
        gemm_bf16<false, false, true><<<g, 256>>>(wkh, wkl, xsh, xsl, nullptr,
                                                  kvh, kvl, nullptr, 2 * DIM, LO);
    }
    // K5: fused attention -> attn split [pix][ch]
    {
        dim3 g(HWQ / 64, NH, BSZ);
        size_t smem = (size_t)6 * 64 * AS * sizeof(u16);  // 55296 B
        cudaFuncSetAttribute(attn_bf16, cudaFuncAttributeMaxDynamicSharedMemorySize, (int)smem);
        attn_bf16<<<g, 128, smem>>>(qh, ql, kvh, kvl, ah, al);
    }
    // K6: out = proj_w @ attn^T + proj_b  (attn split is [pix][ch] => BT)
    {
        dim3 g1((HWQ + 127) / 128, DIM / 128, BSZ);
        gemm_bf16<true, true, false><<<g1, 256>>>(wph, wpl, ah, al, out,
                                                  nullptr, nullptr, proj_b, DIM, HWQ);
    }
}

// round 7
// speedup vs baseline: 3.3894x; 1.1612x over previous
#include <cuda_runtime.h>
#include <cuda_bf16.h>
#include <math.h>
#include <stdint.h>

// ---------------- problem constants ----------------
#define BSZ   8
#define DIM   384
#define HH    56
#define WW    56
#define HWQ   3136
#define NH    6
#define DH    64
#define GRP   3
#define NGD   128
#define HO    28
#define WO    28
#define LO    784
#define SCALE 0.125f

typedef unsigned short u16;

// ---------------- scratch (device globals, no allocs) ----------------
__device__ float  d_q  [(size_t)BSZ * DIM * HWQ];
__device__ u16    d_qh [(size_t)BSZ * DIM * HWQ];
__device__ u16    d_ql [(size_t)BSZ * DIM * HWQ];
__device__ u16    d_xh [(size_t)BSZ * DIM * HWQ];
__device__ u16    d_xl [(size_t)BSZ * DIM * HWQ];
__device__ u16    d_wqh[DIM * DIM],     d_wql[DIM * DIM];
__device__ u16    d_wkh[2 * DIM * DIM], d_wkl[2 * DIM * DIM];
__device__ u16    d_wph[DIM * DIM],     d_wpl[DIM * DIM];
__device__ float  d_off [(size_t)BSZ * GRP * NGD * LO];
__device__ float4 d_grid[(size_t)BSZ * GRP * LO];
__device__ u16    d_xsh[(size_t)BSZ * DIM * LO],     d_xsl[(size_t)BSZ * DIM * LO];
__device__ u16    d_kvh[(size_t)BSZ * 2 * DIM * LO], d_kvl[(size_t)BSZ * 2 * DIM * LO];
__device__ u16    d_ah [(size_t)BSZ * HWQ * DIM],    d_al [(size_t)BSZ * HWQ * DIM];

// ---------------- helpers ----------------
__device__ __forceinline__ void split1(float x, u16& h, u16& l) {
    __nv_bfloat16 bh = __float2bfloat16(x);
    float r = x - __bfloat162float(bh);
    __nv_bfloat16 bl = __float2bfloat16(r);
    h = __bfloat16_as_ushort(bh);
    l = __bfloat16_as_ushort(bl);
}
__device__ __forceinline__ void split_pack(float x, float y, uint32_t& ph, uint32_t& pl) {
    u16 xh, xl, yh, yl;
    split1(x, xh, xl); split1(y, yh, yl);
    ph = ((uint32_t)yh << 16) | xh;
    pl = ((uint32_t)yl << 16) | xl;
}
__device__ __forceinline__ void mma_bf16(float* c, const uint32_t* a, const uint32_t* b) {
    asm volatile(
        "mma.sync.aligned.m16n8k16.row.col.f32.bf16.bf16.f32 "
        "{%0,%1,%2,%3}, {%4,%5,%6,%7}, {%8,%9}, {%0,%1,%2,%3};\n"
        : "+f"(c[0]), "+f"(c[1]), "+f"(c[2]), "+f"(c[3])
        : "r"(a[0]), "r"(a[1]), "r"(a[2]), "r"(a[3]), "r"(b[0]), "r"(b[1]));
}
__device__ __forceinline__ void ldsm4(uint32_t* r, const u16* p) {
    uint32_t a = (uint32_t)__cvta_generic_to_shared(p);
    asm volatile("ldmatrix.sync.aligned.m8n8.x4.shared.b16 {%0,%1,%2,%3}, [%4];"
                 : "=r"(r[0]), "=r"(r[1]), "=r"(r[2]), "=r"(r[3]) : "r"(a));
}
__device__ __forceinline__ void ldsm4t(uint32_t* r, const u16* p) {
    uint32_t a = (uint32_t)__cvta_generic_to_shared(p);
    asm volatile("ldmatrix.sync.aligned.m8n8.x4.trans.shared.b16 {%0,%1,%2,%3}, [%4];"
                 : "=r"(r[0]), "=r"(r[1]), "=r"(r[2]), "=r"(r[3]) : "r"(a));
}
// cp.async 16B with zero-fill when pred false
__device__ __forceinline__ void cpa16(u16* dst, const u16* src, bool pred) {
    uint32_t d = (uint32_t)__cvta_generic_to_shared(dst);
    int sz = pred ? 16 : 0;
    asm volatile("cp.async.cg.shared.global [%0], [%1], 16, %2;"
                 :: "r"(d), "l"(src), "r"(sz));
}
#define CPA_COMMIT asm volatile("cp.async.commit_group;" ::: "memory")
#define CPA_WAIT0  asm volatile("cp.async.wait_group 0;" ::: "memory")

// ---------------- f32 -> (hi,lo) bf16 split ----------------
__global__ void split_kernel(const float* __restrict__ src, u16* __restrict__ h,
                             u16* __restrict__ l, int n4) {
    int i = blockIdx.x * blockDim.x + threadIdx.x;
    if (i >= n4) return;
    float4 v = ((const float4*)src)[i];
    ushort4 hh, ll;
    split1(v.x, hh.x, ll.x); split1(v.y, hh.y, ll.y);
    split1(v.z, hh.z, ll.z); split1(v.w, hh.w, ll.w);
    ((ushort4*)h)[i] = hh; ((ushort4*)l)[i] = ll;
}

// ==================================================================
// GEMM: Y[b] = W(MxK=384) @ X[b](384xN), pre-split bf16 operands,
// cp.async double-buffered. Rows m0<thr2 use 2-term split.
// ==================================================================
#define SST 24
#define BNS 136
#define GBUF (128 * SST)
template<bool BT, bool WF32, bool WSPLIT>
__global__ __launch_bounds__(256, 2) void gemm_bf16(
    const u16* __restrict__ Wh, const u16* __restrict__ Wl,
    const u16* __restrict__ Xh, const u16* __restrict__ Xl,
    float* __restrict__ Yf, u16* __restrict__ Ysh, u16* __restrict__ Ysl,
    const float* __restrict__ bias, int M, int N, int thr2) {
    const int KD = 384;
    __shared__ __align__(16) u16 Ah[2 * GBUF], Al[2 * GBUF];
    __shared__ __align__(16) u16 Bh[2 * GBUF], Bl[2 * GBUF];
    const int bz = blockIdx.z;
    const size_t xoff = (size_t)bz * KD * N;
    const int m0 = blockIdx.y * 128, n0 = blockIdx.x * 128;
    const int tid = threadIdx.x, lane = tid & 31, wid = tid >> 5;
    const int wm = wid & 3, wn = wid >> 2;
    const bool full3 = (m0 >= thr2);
    float c[2][8][4] = {};

    const int arow = tid >> 1, acol = (tid & 1) * 8;
    const int bro = tid >> 4, bcol = (tid & 15) * 8;   // NN
    const int bn2 = tid >> 1, bk2 = (tid & 1) * 8;     // BT

    auto STAGE = [&](int kc, int buf) {
        size_t ao = (size_t)(m0 + arow) * KD + kc * 16 + acol;
        cpa16(&Ah[buf * GBUF + arow * SST + acol], &Wh[ao], true);
        cpa16(&Al[buf * GBUF + arow * SST + acol], &Wl[ao], true);
        if (!BT) {
            bool v = (n0 + bcol) < N;
            size_t o = xoff + (size_t)(kc * 16 + bro) * N + n0 + bcol;
            cpa16(&Bh[buf * GBUF + bro * BNS + bcol], v ? &Xh[o] : Xh, v);
            cpa16(&Bl[buf * GBUF + bro * BNS + bcol], v ? &Xl[o] : Xl, v);
        } else {
            bool v = (n0 + bn2) < N;
            size_t o = xoff + (size_t)(n0 + bn2) * KD + kc * 16 + bk2;
            cpa16(&Bh[buf * GBUF + bn2 * SST + bk2], v ? &Xh[o] : Xh, v);
            cpa16(&Bl[buf * GBUF + bn2 * SST + bk2], v ? &Xl[o] : Xl, v);
        }
    };

    STAGE(0, 0); CPA_COMMIT;
    const int afr = wm * 32 + (lane & 15);
    const int afc = (lane >> 4) << 3;
    for (int kc = 0; kc < 24; kc++) {
        const int buf = kc & 1;
        CPA_WAIT0;
        __syncthreads();
        if (kc < 23) { STAGE(kc + 1, buf ^ 1); CPA_COMMIT; }
        uint32_t ah[2][4], al[2][4];
        #pragma unroll
        for (int mt = 0; mt < 2; mt++) {
            ldsm4(ah[mt], &Ah[buf * GBUF + (afr + mt * 16) * SST + afc]);
            ldsm4(al[mt], &Al[buf * GBUF + (afr + mt * 16) * SST + afc]);
        }
        #pragma unroll
        for (int p = 0; p < 4; p++) {
            uint32_t bh4[4], bl4[4];
            if (!BT) {
                int r = lane & 15, cN = wn * 64 + p * 16 + afc;
                ldsm4t(bh4, &Bh[buf * GBUF + r * BNS + cN]);
                ldsm4t(bl4, &Bl[buf * GBUF + r * BNS + cN]);
            } else {
                int r = wn * 64 + p * 16 + (lane & 7) + afc;
                int cK = ((lane >> 3) & 1) << 3;
                ldsm4(bh4, &Bh[buf * GBUF + r * SST + cK]);
                ldsm4(bl4, &Bl[buf * GBUF + r * SST + cK]);
            }
            #pragma unroll
            for (int sub = 0; sub < 2; sub++) {
                int nt = 2 * p + sub;
                #pragma unroll
                for (int mt = 0; mt < 2; mt++) {
                    mma_bf16(c[mt][nt], ah[mt], &bh4[2 * sub]);
                    mma_bf16(c[mt][nt], al[mt], &bh4[2 * sub]);
                    if (full3) mma_bf16(c[mt][nt], ah[mt], &bl4[2 * sub]);
                }
            }
        }
        __syncthreads();
    }

    const int g = lane >> 2, tq = lane & 3;
    #pragma unroll
    for (int mt = 0; mt < 2; mt++) {
        int row0 = m0 + wm * 32 + mt * 16 + g;
        int row1 = row0 + 8;
        float bv0 = bias ? bias[row0] : 0.f;
        float bv1 = bias ? bias[row1] : 0.f;
        #pragma unroll
        for (int nt = 0; nt < 8; nt++) {
            int col = n0 + wn * 64 + nt * 8 + 2 * tq;
            if (col < N) {
                float v00 = c[mt][nt][0] + bv0, v01 = c[mt][nt][1] + bv0;
                float v10 = c[mt][nt][2] + bv1, v11 = c[mt][nt][3] + bv1;
                size_t o0 = (size_t)bz * M * N + (size_t)row0 * N + col;
                size_t o1 = (size_t)bz * M * N + (size_t)row1 * N + col;
                if (WF32) {
                    *(float2*)&Yf[o0] = make_float2(v00, v01);
                    *(float2*)&Yf[o1] = make_float2(v10, v11);
                }
                if (WSPLIT) {
                    u16 h0, l0, h1, l1;
                    split1(v00, h0, l0); split1(v01, h1, l1);
                    *(uint32_t*)&Ysh[o0] = ((uint32_t)h1 << 16) | h0;
                    *(uint32_t*)&Ysl[o0] = ((uint32_t)l1 << 16) | l0;
                    split1(v10, h0, l0); split1(v11, h1, l1);
                    *(uint32_t*)&Ysh[o1] = ((uint32_t)h1 << 16) | h0;
                    *(uint32_t*)&Ysl[o1] = ((uint32_t)l1 << 16) | l0;
                }
            }
        }
    }
}

// ==================================================================
// Fused flash attention: 2-term QK, 3-term PV, cp.async double-buffered KV.
// smem: Qh,Ql + 2 x {Kh, Vh, Vl}
// ==================================================================
#define AS 72
#define KVB (3 * 64 * AS)
__global__ __launch_bounds__(128, 3) void attn_bf16(
    const u16* __restrict__ qh, const u16* __restrict__ ql,
    const u16* __restrict__ kvh, const u16* __restrict__ kvl,
    u16* __restrict__ oh, u16* __restrict__ ol) {
    extern __shared__ __align__(16) u16 smx[];
    u16* Qh = smx;
    u16* Ql = Qh + 64 * AS;
    u16* KV = Ql + 64 * AS;   // buf b: Kh=KV+b*KVB, Vh=+64*AS, Vl=+2*64*AS
    const int qb = blockIdx.x * 64, h = blockIdx.y, b = blockIdx.z;
    const int tid = threadIdx.x, lane = tid & 31, wid = tid >> 5;
    const int g = lane >> 2, tq = lane & 3;
    const size_t qoff = ((size_t)(b * DIM + h * DH)) * HWQ + qb;
    const size_t koff = ((size_t)(b * 2 * DIM + h * DH)) * LO;
    const size_t voff = ((size_t)(b * 2 * DIM + DIM + h * DH)) * LO;

    auto STAGE_KV = [&](int t, int buf) {
        u16* Kh = KV + buf * KVB;
        u16* Vh = Kh + 64 * AS;
        u16* Vl = Vh + 64 * AS;
        for (int i = tid; i < 512; i += 128) {
            int d = i >> 3, c8 = (i & 7) * 8;
            int key = t * 64 + c8;
            bool v = key < LO;
            size_t gk = koff + (size_t)d * LO + key;
            size_t gv = voff + (size_t)d * LO + key;
            cpa16(&Kh[d * AS + c8], v ? &kvh[gk] : kvh, v);
            cpa16(&Vh[d * AS + c8], v ? &kvh[gv] : kvh, v);
            cpa16(&Vl[d * AS + c8], v ? &kvl[gv] : kvl, v);
        }
    };

    // stage Q [q][d]
    for (int i = tid; i < 4096; i += 128) {
        int d = i >> 6, qq = i & 63;
        Qh[qq * AS + d] = qh[qoff + (size_t)d * HWQ + qq];
        Ql[qq * AS + d] = ql[qoff + (size_t)d * HWQ + qq];
    }
    STAGE_KV(0, 0); CPA_COMMIT;
    __syncthreads();
    uint32_t qfh[4][4], qfl[4][4];
    const int afr = wid * 16 + (lane & 15);
    const int afc = (lane >> 4) << 3;
    #pragma unroll
    for (int kc = 0; kc < 4; kc++) {
        ldsm4(qfh[kc], &Qh[afr * AS + kc * 16 + afc]);
        ldsm4(qfl[kc], &Ql[afr * AS + kc * 16 + afc]);
    }

    float o[8][4] = {};
    float mrow0 = -1e30f, mrow1 = -1e30f, lrow0 = 0.f, lrow1 = 0.f;

    for (int t = 0; t < 13; t++) {
        const int buf = t & 1;
        u16* Kh = KV + buf * KVB;
        u16* Vh = Kh + 64 * AS;
        u16* Vl = Vh + 64 * AS;
        CPA_WAIT0;
        __syncthreads();
        if (t < 12) { STAGE_KV(t + 1, buf ^ 1); CPA_COMMIT; }

        float s[8][4] = {};
        #pragma unroll
        for (int kc = 0; kc < 4; kc++) {
            #pragma unroll
            for (int p = 0; p < 4; p++) {
                uint32_t bh4[4];
                int r = kc * 16 + (lane & 15), cN = p * 16 + afc;
                ldsm4t(bh4, &Kh[r * AS + cN]);
                #pragma unroll
                for (int sub = 0; sub < 2; sub++) {
                    int nt = 2 * p + sub;
                    mma_bf16(s[nt], qfh[kc], &bh4[2 * sub]);
                    mma_bf16(s[nt], qfl[kc], &bh4[2 * sub]);
                }
            }
        }
        #pragma unroll
        for (int nt = 0; nt < 8; nt++) {
            s[nt][0] *= SCALE; s[nt][1] *= SCALE;
            s[nt][2] *= SCALE; s[nt][3] *= SCALE;
        }
        if (t == 12) {
            #pragma unroll
            for (int nt = 0; nt < 8; nt++) {
                int key0 = 768 + nt * 8 + 2 * tq;
                if (key0 >= LO) { s[nt][0] = s[nt][1] = s[nt][2] = s[nt][3] = -1e30f; }
            }
        }
        // online softmax (rows g, g+8)
        float mx0 = -1e30f, mx1 = -1e30f;
        #pragma unroll
        for (int nt = 0; nt < 8; nt++) {
            mx0 = fmaxf(mx0, fmaxf(s[nt][0], s[nt][1]));
            mx1 = fmaxf(mx1, fmaxf(s[nt][2], s[nt][3]));
        }
        mx0 = fmaxf(mx0, __shfl_xor_sync(0xffffffffu, mx0, 1));
        mx0 = fmaxf(mx0, __shfl_xor_sync(0xffffffffu, mx0, 2));
        mx1 = fmaxf(mx1, __shfl_xor_sync(0xffffffffu, mx1, 1));
        mx1 = fmaxf(mx1, __shfl_xor_sync(0xffffffffu, mx1, 2));
        float nm0 = fmaxf(mrow0, mx0), nm1 = fmaxf(mrow1, mx1);
        float corr0 = __expf(mrow0 - nm0), corr1 = __expf(mrow1 - nm1);
        mrow0 = nm0; mrow1 = nm1;
        float ps0 = 0.f, ps1 = 0.f;
        #pragma unroll
        for (int nt = 0; nt < 8; nt++) {
            s[nt][0] = __expf(s[nt][0] - nm0); ps0 += s[nt][0];
            s[nt][1] = __expf(s[nt][1] - nm0); ps0 += s[nt][1];
            s[nt][2] = __expf(s[nt][2] - nm1); ps1 += s[nt][2];
            s[nt][3] = __expf(s[nt][3] - nm1); ps1 += s[nt][3];
        }
        ps0 += __shfl_xor_sync(0xffffffffu, ps0, 1);
        ps0 += __shfl_xor_sync(0xffffffffu, ps0, 2);
        ps1 += __shfl_xor_sync(0xffffffffu, ps1, 1);
        ps1 += __shfl_xor_sync(0xffffffffu, ps1, 2);
        lrow0 = lrow0 * corr0 + ps0;
        lrow1 = lrow1 * corr1 + ps1;
        #pragma unroll
        for (int nt = 0; nt < 8; nt++) {
            o[nt][0] *= corr0; o[nt][1] *= corr0;
            o[nt][2] *= corr1; o[nt][3] *= corr1;
        }
        // P fragments + PV (3-term)
        uint32_t ph[4][4], pl[4][4];
        #pragma unroll
        for (int kc = 0; kc < 4; kc++) {
            split_pack(s[2 * kc][0],     s[2 * kc][1],     ph[kc][0], pl[kc][0]);
            split_pack(s[2 * kc][2],     s[2 * kc][3],     ph[kc][1], pl[kc][1]);
            split_pack(s[2 * kc + 1][0], s[2 * kc + 1][1], ph[kc][2], pl[kc][2]);
            split_pack(s[2 * kc + 1][2], s[2 * kc + 1][3], ph[kc][3], pl[kc][3]);
        }
        #pragma unroll
        for (int kc = 0; kc < 4; kc++) {
            #pragma unroll
            for (int p = 0; p < 4; p++) {
                uint32_t vh4[4], vl4[4];
                int vr = p * 16 + (lane & 7) + afc;
                int vc = kc * 16 + (((lane >> 3) & 1) << 3);
                ldsm4(vh4, &Vh[vr * AS + vc]);
                ldsm4(vl4, &Vl[vr * AS + vc]);
                #pragma unroll
                for (int sub = 0; sub < 2; sub++) {
                    int nt = 2 * p + sub;
                    mma_bf16(o[nt], ph[kc], &vh4[2 * sub]);
                    mma_bf16(o[nt], pl[kc], &vh4[2 * sub]);
                    mma_bf16(o[nt], ph[kc], &vl4[2 * sub]);
                }
            }
        }
        __syncthreads();
    }
    float inv0 = 1.f / lrow0, inv1 = 1.f / lrow1;
    size_t base = (size_t)b * HWQ + qb;
    int rlo = wid * 16 + g, rhi = rlo + 8;
    #pragma unroll
    for (int nt = 0; nt < 8; nt++) {
        int d = h * DH + nt * 8 + 2 * tq;
        u16 h0, l0, h1, l1;
        split1(o[nt][0] * inv0, h0, l0); split1(o[nt][1] * inv0, h1, l1);
        *(uint32_t*)&oh[(base + rlo) * DIM + d] = ((uint32_t)h1 << 16) | h0;
        *(uint32_t*)&ol[(base + rlo) * DIM + d] = ((uint32_t)l1 << 16) | l0;
        split1(o[nt][2] * inv1, h0, l0); split1(o[nt][3] * inv1, h1, l1);
        *(uint32_t*)&oh[(base + rhi) * DIM + d] = ((uint32_t)h1 << 16) | h0;
        *(uint32_t*)&ol[(base + rhi) * DIM + d] = ((uint32_t)l1 << 16) | l0;
    }
}

// ---------------- depthwise 5x5 s2 + bias + BN + exact GELU ----------------
__global__ void dw_bn_gelu_kernel(const float* __restrict__ q,
                                  const float* __restrict__ dw_w, const float* __restrict__ dw_b,
                                  const float* __restrict__ bn_w, const float* __restrict__ bn_b,
                                  const float* __restrict__ bn_mean, const float* __restrict__ bn_var,
                                  float* __restrict__ off) {
    int idx = blockIdx.x * blockDim.x + threadIdx.x;
    const int TOT = BSZ * GRP * NGD * LO;
    if (idx >= TOT) return;
    int pix = idx % LO;
    int c   = (idx / LO) % NGD;
    int n   = idx / (LO * NGD);
    int oy = pix / WO, ox = pix % WO;
    int b = n / GRP, g = n % GRP;
    const float* plane = q + ((size_t)(b * DIM + g * NGD + c)) * HWQ;
    const float* wk = dw_w + c * 25;
    float s = 0.f;
    #pragma unroll
    for (int ky = 0; ky < 5; ky++) {
        int iy = oy * 2 + ky - 2;
        if (iy < 0 || iy >= HH) continue;
        #pragma unroll
        for (int kx = 0; kx < 5; kx++) {
            int ix = ox * 2 + kx - 2;
            if (ix >= 0 && ix < WW) s = fmaf(plane[iy * WW + ix], wk[ky * 5 + kx], s);
        }
    }
    s += dw_b[c];
    s = (s - bn_mean[c]) * (bn_w[c] * rsqrtf(bn_var[c] + 1e-6f)) + bn_b[c];
    s = 0.5f * s * (1.0f + erff(s * 0.70710678118654752f));
    off[idx] = s;
}

// ---------------- pointwise 128->3 + offset/grid math ----------------
__global__ void pw_grid_kernel(const float* __restrict__ off, const float* __restrict__ pw_w,
                               float4* __restrict__ grid4) {
    int idx = blockIdx.x * blockDim.x + threadIdx.x;
    const int TOT = BSZ * GRP * LO;
    if (idx >= TOT) return;
    int n = idx / LO, pix = idx % LO;
    const float* base = off + (size_t)n * NGD * LO + pix;
    float o0 = 0.f, o1 = 0.f, o2 = 0.f;
    #pragma unroll 4
    for (int c = 0; c < NGD; c++) {
        float v = base[(size_t)c * LO];
        o0 = fmaf(v, pw_w[c], o0);
        o1 = fmaf(v, pw_w[NGD + c], o1);
        o2 = fmaf(v, pw_w[2 * NGD + c], o2);
    }
    int oy = pix / WO, ox = pix % WO;
    float ry = ((0.5f + (float)oy) / (float)HO) * 2.f - 1.f;
    float rx = ((0.5f + (float)ox) / (float)WO) * 2.f - 1.f;
    float posy = tanhf(o0) * (2.0f / (float)HO) + ry;
    float posx = tanhf(o1) * (2.0f / (float)WO) + rx;
    float gx = (posx + 1.f) * 0.5f * (float)(WW - 1);
    float gy = (posy + 1.f) * 0.5f * (float)(HH - 1);
    float sig = 1.f / (1.f + expf(-o2));
    float mod = 1.f / (1.f + expf(-sig));
    grid4[idx] = make_float4(gx, gy, mod, 0.f);
}

// ---------------- bilinear grid sample * modulation -> split bf16 ----------------
__global__ void sample_kernel(const float* __restrict__ x, const float4* __restrict__ grid4,
                              u16* __restrict__ xsh, u16* __restrict__ xsl) {
    int nc = blockIdx.x;
    int pix = blockIdx.y * blockDim.x + threadIdx.x;
    if (pix >= LO) return;
    int c = nc & (NGD - 1), n = nc >> 7;
    int b = n / GRP, g = n % GRP;
    float4 gq = grid4[(size_t)n * LO + pix];
    float gx = gq.x, gy = gq.y, mod = gq.z;
    float x0f = floorf(gx), y0f = floorf(gy);
    float x1f = x0f + 1.f, y1f = y0f + 1.f;
    const float* plane = x + ((size_t)(b * DIM + g * NGD + c)) * HWQ;

    float t00 = 0.f, t01 = 0.f, t10 = 0.f, t11 = 0.f;
    bool vx0 = (x0f >= 0.f) && (x0f <= (float)(WW - 1));
    bool vx1 = (x1f >= 0.f) && (x1f <= (float)(WW - 1));
    bool vy0 = (y0f >= 0.f) && (y0f <= (float)(HH - 1));
    bool vy1 = (y1f >= 0.f) && (y1f <= (float)(HH - 1));
    int xi0 = (int)fminf(fmaxf(x0f, 0.f), (float)(WW - 1));
    int xi1 = (int)fminf(fmaxf(x1f, 0.f), (float)(WW - 1));
    int yi0 = (int)fminf(fmaxf(y0f, 0.f), (float)(HH - 1));
    int yi1 = (int)fminf(fmaxf(y1f, 0.f), (float)(HH - 1));
    if (vy0 && vx0) t00 = plane[yi0 * WW + xi0];
    if (vy1 && vx0) t10 = plane[yi1 * WW + xi0];
    if (vy0 && vx1) t01 = plane[yi0 * WW + xi1];
    if (vy1 && vx1) t11 = plane[yi1 * WW + xi1];

    float v = t00 * (x1f - gx) * (y1f - gy)
            + t10 * (x1f - gx) * (gy - y0f)
            + t01 * (gx - x0f) * (y1f - gy)
            + t11 * (gx - x0f) * (gy - y0f);
    v *= mod;
    u16 hh, ll; split1(v, hh, ll);
    size_t o = ((size_t)(b * DIM + g * NGD + c)) * LO + pix;
    xsh[o] = hh; xsl[o] = ll;
}

// ---------------- launch ----------------
extern "C" void kernel_launch(void* const* d_in, const int* in_sizes, int n_in,
                              void* d_out, int out_size) {
    const float* x      = (const float*)d_in[0];
    const float* q_w    = (const float*)d_in[1];
    const float* kv_w   = (const float*)d_in[2];
    const float* proj_w = (const float*)d_in[3];
    const float* proj_b = (const float*)d_in[4];
    const float* dw_w   = (const float*)d_in[5];
    const float* dw_b   = (const float*)d_in[6];
    const float* bn_w   = (const float*)d_in[7];
    const float* bn_b   = (const float*)d_in[8];
    const float* bn_mean= (const float*)d_in[9];
    const float* bn_var = (const float*)d_in[10];
    const float* pw_w   = (const float*)d_in[11];
    float* out = (float*)d_out;

    float *q, *off; float4* grid;
    u16 *qh, *ql, *xh, *xl, *wqh, *wql, *wkh, *wkl, *wph, *wpl;
    u16 *xsh, *xsl, *kvh, *kvl, *ah, *al;
    cudaGetSymbolAddress((void**)&q,    d_q);
    cudaGetSymbolAddress((void**)&off,  d_off);
    cudaGetSymbolAddress((void**)&grid, d_grid);
    cudaGetSymbolAddress((void**)&qh,   d_qh);
    cudaGetSymbolAddress((void**)&ql,   d_ql);
    cudaGetSymbolAddress((void**)&xh,   d_xh);
    cudaGetSymbolAddress((void**)&xl,   d_xl);
    cudaGetSymbolAddress((void**)&wqh,  d_wqh);
    cudaGetSymbolAddress((void**)&wql,  d_wql);
    cudaGetSymbolAddress((void**)&wkh,  d_wkh);
    cudaGetSymbolAddress((void**)&wkl,  d_wkl);
    cudaGetSymbolAddress((void**)&wph,  d_wph);
    cudaGetSymbolAddress((void**)&wpl,  d_wpl);
    cudaGetSymbolAddress((void**)&xsh,  d_xsh);
    cudaGetSymbolAddress((void**)&xsl,  d_xsl);
    cudaGetSymbolAddress((void**)&kvh,  d_kvh);
    cudaGetSymbolAddress((void**)&kvl,  d_kvl);
    cudaGetSymbolAddress((void**)&ah,   d_ah);
    cudaGetSymbolAddress((void**)&al,   d_al);

    // pre-split x and weights
    {
        int n4 = BSZ * DIM * HWQ / 4;
        split_kernel<<<(n4 + 255) / 256, 256>>>(x, xh, xl, n4);
        int w4 = DIM * DIM / 4;
        split_kernel<<<(w4 + 255) / 256, 256>>>(q_w, wqh, wql, w4);
        split_kernel<<<(2 * w4 + 255) / 256, 256>>>(kv_w, wkh, wkl, 2 * w4);
        split_kernel<<<(w4 + 255) / 256, 256>>>(proj_w, wph, wpl, w4);
    }
    // K1: q = q_w @ x  -> f32 + split (3-term everywhere)
    {
        dim3 g1((HWQ + 127) / 128, DIM / 128, BSZ);
        gemm_bf16<false, true, true><<<g1, 256>>>(wqh, wql, xh, xl, q, qh, ql,
                                                  nullptr, DIM, HWQ, 0);
    }
    // K2: depthwise conv + bias + BN + gelu
    {
        int tot = BSZ * GRP * NGD * LO;
        dw_bn_gelu_kernel<<<(tot + 255) / 256, 256>>>(q, dw_w, dw_b, bn_w, bn_b,
                                                      bn_mean, bn_var, off);
    }
    // K3a: pointwise + grid
    {
        int tot = BSZ * GRP * LO;
        pw_grid_kernel<<<(tot + 255) / 256, 256>>>(off, pw_w, grid);
    }
    // K3b: bilinear sampling -> xs split
    {
        dim3 g((BSZ * GRP * NGD), (LO + 255) / 256);
        sample_kernel<<<g, 256>>>(x, grid, xsh, xsl);
    }
    // K4: kv = kv_w @ xs -> split only (k-half m0<384 uses 2-term)
    {
        dim3 g((LO + 127) / 128, (2 * DIM) / 128, BSZ);
        gemm_bf16<false, false, true><<<g, 256>>>(wkh, wkl, xsh, xsl, nullptr,
                                                  kvh, kvl, nullptr, 2 * DIM, LO, DIM);
    }
    // K5: fused attention -> attn split [pix][ch]
    {
        dim3 g(HWQ / 64, NH, BSZ);
        size_t smem = (size_t)(2 * 64 * AS + 2 * KVB) * sizeof(u16);  // 73728 B
        cudaFuncSetAttribute(attn_bf16, cudaFuncAttributeMaxDynamicSharedMemorySize, (int)smem);
        attn_bf16<<<g, 128, smem>>>(qh, ql, kvh, kvl, ah, al);
    }
    // K6: out = proj_w @ attn^T + proj_b  (3-term)
    {
        dim3 g1((HWQ + 127) / 128, DIM / 128, BSZ);
        gemm_bf16<true, true, false><<<g1, 256>>>(wph, wpl, ah, al, out,
                                                  nullptr, nullptr, proj_b, DIM, HWQ, 0);
    }
}